// round 2
// baseline (speedup 1.0000x reference)
#include <cuda_runtime.h>
#include <math.h>

// ---------------- problem constants ----------------
namespace {
constexpr int B_    = 32;
constexpr int NSEQ  = 4096;
constexpr int C     = 256;
constexpr int WSZ   = 64;
constexpr int SH    = 32;
constexpr int H_    = 8;
constexpr int NWIN  = 64;                 // N / WS
constexpr int ROWS  = B_ * NSEQ;          // 131072
constexpr int BW    = B_ * NWIN;          // 2048 windows
constexpr int HID   = 1024;
constexpr float SCALE = 0.17677669529663687f;  // 32^-0.5
}

// ---------------- scratch (device globals; allocation-free) ----------------
__device__ float g_hs  [(size_t)ROWS * C];        // LN1(+shift) output / reused for LN2 output
__device__ float g_qkv [(size_t)ROWS * 3 * C];    // qkv rows, cols = (s,h,d)
__device__ float g_attn[(size_t)ROWS * C];        // attention out (+ LePE accumulated)
__device__ float g_x1  [(size_t)ROWS * C];        // first residual
__device__ float g_m1  [(size_t)ROWS * HID];      // FFN hidden
__device__ float g_lepew[(size_t)C * 3 * C];      // pos_w re-laid-out to [o][t*256+i]

// ---------------- pos_w re-layout: [o][i][t] -> [o][t*256+i] ----------------
__global__ void posw_kernel(const float* __restrict__ pw) {
    int idx = blockIdx.x * 256 + threadIdx.x;      // 196608 total
    int o = idx / 768, kk = idx % 768;
    int t = kk >> 8, i = kk & 255;
    g_lepew[idx] = pw[(size_t)o * 768 + i * 3 + t];
}

// ---------------- LayerNorm (optionally reading with cyclic shift) ----------------
// out[row] = LN(x[b, (n+shift) mod N])
__global__ __launch_bounds__(64) void ln_kernel(const float* __restrict__ x,
                                                const float* __restrict__ w,
                                                const float* __restrict__ bvec,
                                                float* __restrict__ out, int shift) {
    int row = blockIdx.x;
    int b = row >> 12, n = row & 4095;
    int src = (b << 12) | ((n + shift) & 4095);
    const float4* xin = reinterpret_cast<const float4*>(x + (size_t)src * C);
    int t = threadIdx.x;
    float4 v = xin[t];
    float s = v.x + v.y + v.z + v.w;
    float q = v.x * v.x + v.y * v.y + v.z * v.z + v.w * v.w;
#pragma unroll
    for (int o = 16; o > 0; o >>= 1) {
        s += __shfl_xor_sync(0xffffffffu, s, o);
        q += __shfl_xor_sync(0xffffffffu, q, o);
    }
    __shared__ float sh[4];
    if ((t & 31) == 0) { sh[t >> 5] = s; sh[2 + (t >> 5)] = q; }
    __syncthreads();
    s = sh[0] + sh[1]; q = sh[2] + sh[3];
    float mean = s * (1.0f / C);
    float var  = q * (1.0f / C) - mean * mean;
    float rstd = rsqrtf(var + 1e-5f);
    float4 wv = reinterpret_cast<const float4*>(w)[t];
    float4 bv = reinterpret_cast<const float4*>(bvec)[t];
    float4 o4;
    o4.x = (v.x - mean) * rstd * wv.x + bv.x;
    o4.y = (v.y - mean) * rstd * wv.y + bv.y;
    o4.z = (v.z - mean) * rstd * wv.z + bv.z;
    o4.w = (v.w - mean) * rstd * wv.w + bv.w;
    reinterpret_cast<float4*>(out + (size_t)row * C)[t] = o4;
}

// ---------------- windowed attention: one (window, head) per block ----------------
__global__ __launch_bounds__(64) void attn_kernel(const float* __restrict__ qkv,
                                                  const float* __restrict__ mask,
                                                  float* __restrict__ out) {
    int wh = blockIdx.x;
    int bw = wh >> 3;          // window id (global)
    int h  = wh & 7;           // head
    int wIdx = bw & 63;        // window index within sequence (for mask)
    int t = threadIdx.x;       // query row

    __shared__ float ks[64][33];
    __shared__ float vs[64][33];
    __shared__ float ps[64][65];

    const float* rowp = qkv + ((size_t)bw * 64 + t) * 768 + h * 32;
    float qr[32];
#pragma unroll
    for (int c = 0; c < 8; c++) {
        float4 kv = *reinterpret_cast<const float4*>(rowp + 256 + c * 4);
        ks[t][c * 4 + 0] = kv.x; ks[t][c * 4 + 1] = kv.y;
        ks[t][c * 4 + 2] = kv.z; ks[t][c * 4 + 3] = kv.w;
        float4 vv = *reinterpret_cast<const float4*>(rowp + 512 + c * 4);
        vs[t][c * 4 + 0] = vv.x; vs[t][c * 4 + 1] = vv.y;
        vs[t][c * 4 + 2] = vv.z; vs[t][c * 4 + 3] = vv.w;
        float4 qv = *reinterpret_cast<const float4*>(rowp + c * 4);
        qr[c * 4 + 0] = qv.x * SCALE; qr[c * 4 + 1] = qv.y * SCALE;
        qr[c * 4 + 2] = qv.z * SCALE; qr[c * 4 + 3] = qv.w * SCALE;
    }
    __syncthreads();

    const float* mrow = mask + ((size_t)wIdx * 64 + t) * 64;
    float mx = -1e30f;
#pragma unroll 4
    for (int j = 0; j < 64; j++) {
        float s = 0.f;
#pragma unroll
        for (int d = 0; d < 32; d++) s = fmaf(qr[d], ks[j][d], s);
        s += mrow[j];
        ps[t][j] = s;
        mx = fmaxf(mx, s);
    }
    float sum = 0.f;
#pragma unroll 4
    for (int j = 0; j < 64; j++) {
        float e = __expf(ps[t][j] - mx);
        ps[t][j] = e;
        sum += e;
    }
    float inv = 1.f / sum;

    float acc[32];
#pragma unroll
    for (int d = 0; d < 32; d++) acc[d] = 0.f;
#pragma unroll 4
    for (int j = 0; j < 64; j++) {
        float p = ps[t][j];
#pragma unroll
        for (int d = 0; d < 32; d++) acc[d] = fmaf(p, vs[j][d], acc[d]);
    }
    float* orow = out + ((size_t)bw * 64 + t) * 256 + h * 32;
#pragma unroll
    for (int d = 0; d < 32; d++) orow[d] = acc[d] * inv;
}

// ---------------- templated NT SGEMM, 128x128x16, fused epilogues ----------------
// MODE 0: QKV      (bias, store [r*768+c])
// MODE 1: LEPE     (shifted/masked A gather within window; C += acc + bias)
// MODE 2: PROJ     (bias; unroll shift; C[perm] = extra[perm] + acc)
// MODE 3: FC1+GELU (bias, exact gelu)
// MODE 4: FC2      (bias + extra residual)
template <int MODE>
__global__ __launch_bounds__(256) void gemm_kernel(
    const float* __restrict__ A, const float* __restrict__ W,
    const float* __restrict__ bias, float* __restrict__ Cout,
    const float* __restrict__ extra, int Kin, int Kout) {
    __shared__ float As[16][132];
    __shared__ float Bs[16][132];
    const int tid = threadIdx.x;
    const int m0 = blockIdx.y * 128;
    const int n0 = blockIdx.x * 128;
    const int tm = (tid >> 4) * 8;
    const int tn = (tid & 15) * 8;

    float acc[8][8];
#pragma unroll
    for (int i = 0; i < 8; i++)
#pragma unroll
        for (int j = 0; j < 8; j++) acc[i][j] = 0.f;

    for (int k0 = 0; k0 < Kin; k0 += 16) {
#pragma unroll
        for (int l = 0; l < 2; l++) {
            int p = tid + l * 256;
            int row = p >> 2;
            int c4 = (p & 3) * 4;
            float4 av;
            if (MODE == 1) {
                // A points at v-part (qkv+512), lda=768; segment t = k0/256, row shift d=t-1
                int d = (k0 >> 8) - 1;
                int R = m0 + row;
                int w = R & 63;
                if ((unsigned)(w + d) < 64u)
                    av = *reinterpret_cast<const float4*>(
                        A + (size_t)(R + d) * 768 + ((k0 + c4) & 255));
                else
                    av = make_float4(0.f, 0.f, 0.f, 0.f);
            } else {
                av = *reinterpret_cast<const float4*>(A + (size_t)(m0 + row) * Kin + k0 + c4);
            }
            As[c4 + 0][row] = av.x; As[c4 + 1][row] = av.y;
            As[c4 + 2][row] = av.z; As[c4 + 3][row] = av.w;
            float4 wv = *reinterpret_cast<const float4*>(W + (size_t)(n0 + row) * Kin + k0 + c4);
            Bs[c4 + 0][row] = wv.x; Bs[c4 + 1][row] = wv.y;
            Bs[c4 + 2][row] = wv.z; Bs[c4 + 3][row] = wv.w;
        }
        __syncthreads();
#pragma unroll
        for (int kk = 0; kk < 16; kk++) {
            float a[8], b[8];
            *reinterpret_cast<float4*>(a)     = *reinterpret_cast<const float4*>(&As[kk][tm]);
            *reinterpret_cast<float4*>(a + 4) = *reinterpret_cast<const float4*>(&As[kk][tm + 4]);
            *reinterpret_cast<float4*>(b)     = *reinterpret_cast<const float4*>(&Bs[kk][tn]);
            *reinterpret_cast<float4*>(b + 4) = *reinterpret_cast<const float4*>(&Bs[kk][tn + 4]);
#pragma unroll
            for (int i = 0; i < 8; i++)
#pragma unroll
                for (int j = 0; j < 8; j++) acc[i][j] = fmaf(a[i], b[j], acc[i][j]);
        }
        __syncthreads();
    }

#pragma unroll
    for (int i = 0; i < 8; i++) {
        int r = m0 + tm + i;
#pragma unroll
        for (int j = 0; j < 8; j++) {
            int c = n0 + tn + j;
            float val = acc[i][j] + bias[c];
            if (MODE == 0) {
                Cout[(size_t)r * 768 + c] = val;
            } else if (MODE == 1) {
                size_t o = (size_t)r * 256 + c;
                Cout[o] += val;
            } else if (MODE == 2) {
                int b = r >> 12, n = r & 4095;
                int n2 = (n + SH) & 4095;               // reverse cyclic shift
                size_t o = ((size_t)((b << 12) | n2)) * 256 + c;
                Cout[o] = extra[o] + val;               // x + attn-branch
            } else if (MODE == 3) {
                float g = 0.5f * val * (1.f + erff(val * 0.70710678118654752f));
                Cout[(size_t)r * 1024 + c] = g;
            } else {
                size_t o = (size_t)r * 256 + c;
                Cout[o] = val + extra[o];               // x1 + mlp
            }
        }
    }
}

// ---------------- launch ----------------
extern "C" void kernel_launch(void* const* d_in, const int* in_sizes, int n_in,
                              void* d_out, int out_size) {
    const float* x     = (const float*)d_in[0];
    const float* mask  = (const float*)d_in[1];
    const float* n1w   = (const float*)d_in[2];
    const float* n1b   = (const float*)d_in[3];
    const float* qkvw  = (const float*)d_in[4];
    const float* qkvb  = (const float*)d_in[5];
    const float* posw  = (const float*)d_in[6];
    const float* posb  = (const float*)d_in[7];
    const float* projw = (const float*)d_in[8];
    const float* projb = (const float*)d_in[9];
    const float* n2w   = (const float*)d_in[10];
    const float* n2b   = (const float*)d_in[11];
    const float* fc1w  = (const float*)d_in[12];
    const float* fc1b  = (const float*)d_in[13];
    const float* fc2w  = (const float*)d_in[14];
    const float* fc2b  = (const float*)d_in[15];
    float* out = (float*)d_out;

    float *hs, *qkv, *attn, *x1, *m1, *lepew;
    cudaGetSymbolAddress((void**)&hs,    g_hs);
    cudaGetSymbolAddress((void**)&qkv,   g_qkv);
    cudaGetSymbolAddress((void**)&attn,  g_attn);
    cudaGetSymbolAddress((void**)&x1,    g_x1);
    cudaGetSymbolAddress((void**)&m1,    g_m1);
    cudaGetSymbolAddress((void**)&lepew, g_lepew);

    // pos_w re-layout (tiny)
    posw_kernel<<<768, 256>>>(posw);
    // LN1 fused with cyclic shift (-SHIFT roll)
    ln_kernel<<<ROWS, 64>>>(x, n1w, n1b, hs, SH);
    // QKV projection
    gemm_kernel<0><<<dim3(6, ROWS / 128), 256>>>(hs, qkvw, qkvb, qkv, nullptr, 256, 768);
    // windowed attention
    attn_kernel<<<BW * H_, 64>>>(qkv, mask, attn);
    // LePE conv as masked-gather GEMM, accumulated into attn output
    gemm_kernel<1><<<dim3(2, ROWS / 128), 256>>>(qkv + 512, lepew, posb, attn, nullptr, 768, 256);
    // proj + reverse shift + first residual -> x1
    gemm_kernel<2><<<dim3(2, ROWS / 128), 256>>>(attn, projw, projb, x1, x, 256, 256);
    // LN2 (no shift), reuse hs
    ln_kernel<<<ROWS, 64>>>(x1, n2w, n2b, hs, 0);
    // FC1 + exact GELU
    gemm_kernel<3><<<dim3(8, ROWS / 128), 256>>>(hs, fc1w, fc1b, m1, nullptr, 256, 1024);
    // FC2 + second residual -> output
    gemm_kernel<4><<<dim3(2, ROWS / 128), 256>>>(m1, fc2w, fc2b, out, x1, 1024, 256);
}

// round 3
// speedup vs baseline: 2.7686x; 2.7686x over previous
#include <cuda_runtime.h>
#include <cuda_bf16.h>
#include <math.h>
#include <stdint.h>

// ---------------- problem constants ----------------
namespace {
constexpr int B_    = 32;
constexpr int NSEQ  = 4096;
constexpr int C     = 256;
constexpr int SH    = 32;
constexpr int H_    = 8;
constexpr int NWIN  = 64;
constexpr int ROWS  = B_ * NSEQ;          // 131072
constexpr int BW    = B_ * NWIN;          // 2048 windows
constexpr int HID   = 1024;
constexpr float SCALE = 0.17677669529663687f;  // 32^-0.5

// bf16 weight buffer offsets
constexpr size_t OFF_QKVW = 0;                       // 768*256
constexpr size_t OFF_LEPE = 196608;                  // 256*768
constexpr size_t OFF_PROJ = 393216;                  // 256*256
constexpr size_t OFF_FC1  = 458752;                  // 1024*256
constexpr size_t OFF_FC2  = 720896;                  // 256*1024
constexpr size_t WBF_TOT  = 983040;
}

// ---------------- scratch (device globals; allocation-free) ----------------
__device__ float g_hs  [(size_t)ROWS * C];
__device__ float g_qkv [(size_t)ROWS * 3 * C];
__device__ float g_attn[(size_t)ROWS * C];
__device__ float g_x1  [(size_t)ROWS * C];
__device__ float g_m1  [(size_t)ROWS * HID];
__device__ __nv_bfloat16 g_wbf[WBF_TOT];

// ---------------- weight conversion ----------------
__global__ void cvt_kernel(const float* __restrict__ src, __nv_bfloat16* __restrict__ dst, int n) {
    int i = blockIdx.x * 256 + threadIdx.x;
    if (i < n) dst[i] = __float2bfloat16(src[i]);
}

// pos_w [o][i][t] -> bf16 [o][t*256+i]
__global__ void posw_kernel(const float* __restrict__ pw, __nv_bfloat16* __restrict__ dst) {
    int idx = blockIdx.x * 256 + threadIdx.x;      // 196608
    int o = idx / 768, kk = idx % 768;
    int t = kk >> 8, i = kk & 255;
    dst[idx] = __float2bfloat16(pw[(size_t)o * 768 + i * 3 + t]);
}

// ---------------- LayerNorm (optional cyclic-shift read) ----------------
__global__ __launch_bounds__(64) void ln_kernel(const float* __restrict__ x,
                                                const float* __restrict__ w,
                                                const float* __restrict__ bvec,
                                                float* __restrict__ out, int shift) {
    int row = blockIdx.x;
    int b = row >> 12, n = row & 4095;
    int src = (b << 12) | ((n + shift) & 4095);
    const float4* xin = reinterpret_cast<const float4*>(x + (size_t)src * C);
    int t = threadIdx.x;
    float4 v = xin[t];
    float s = v.x + v.y + v.z + v.w;
    float q = v.x * v.x + v.y * v.y + v.z * v.z + v.w * v.w;
#pragma unroll
    for (int o = 16; o > 0; o >>= 1) {
        s += __shfl_xor_sync(0xffffffffu, s, o);
        q += __shfl_xor_sync(0xffffffffu, q, o);
    }
    __shared__ float sh[4];
    if ((t & 31) == 0) { sh[t >> 5] = s; sh[2 + (t >> 5)] = q; }
    __syncthreads();
    s = sh[0] + sh[1]; q = sh[2] + sh[3];
    float mean = s * (1.0f / C);
    float var  = q * (1.0f / C) - mean * mean;
    float rstd = rsqrtf(var + 1e-5f);
    float4 wv = reinterpret_cast<const float4*>(w)[t];
    float4 bv = reinterpret_cast<const float4*>(bvec)[t];
    float4 o4;
    o4.x = (v.x - mean) * rstd * wv.x + bv.x;
    o4.y = (v.y - mean) * rstd * wv.y + bv.y;
    o4.z = (v.z - mean) * rstd * wv.z + bv.z;
    o4.w = (v.w - mean) * rstd * wv.w + bv.w;
    reinterpret_cast<float4*>(out + (size_t)row * C)[t] = o4;
}

// ---------------- windowed attention: single-pass unnormalized softmax ------
__global__ __launch_bounds__(64) void attn_kernel(const float* __restrict__ qkv,
                                                  const float* __restrict__ mask,
                                                  float* __restrict__ out) {
    int wh = blockIdx.x;
    int bw = wh >> 3;          // window id
    int h  = wh & 7;           // head
    int wIdx = bw & 63;        // window index within sequence
    int t = threadIdx.x;       // query row

    __shared__ float ks[64][33];
    __shared__ float vs[64][33];

    const float* rowp = qkv + ((size_t)bw * 64 + t) * 768 + h * 32;
    float qr[32];
#pragma unroll
    for (int c = 0; c < 8; c++) {
        float4 kv = *reinterpret_cast<const float4*>(rowp + 256 + c * 4);
        ks[t][c * 4 + 0] = kv.x; ks[t][c * 4 + 1] = kv.y;
        ks[t][c * 4 + 2] = kv.z; ks[t][c * 4 + 3] = kv.w;
        float4 vv = *reinterpret_cast<const float4*>(rowp + 512 + c * 4);
        vs[t][c * 4 + 0] = vv.x; vs[t][c * 4 + 1] = vv.y;
        vs[t][c * 4 + 2] = vv.z; vs[t][c * 4 + 3] = vv.w;
        float4 qv = *reinterpret_cast<const float4*>(rowp + c * 4);
        qr[c * 4 + 0] = qv.x * SCALE; qr[c * 4 + 1] = qv.y * SCALE;
        qr[c * 4 + 2] = qv.z * SCALE; qr[c * 4 + 3] = qv.w * SCALE;
    }
    __syncthreads();

    const float* mrow = mask + ((size_t)wIdx * 64 + t) * 64;
    float sum = 0.f;
    float acc[32];
#pragma unroll
    for (int d = 0; d < 32; d++) acc[d] = 0.f;
#pragma unroll 2
    for (int j = 0; j < 64; j++) {
        float s = mrow[j];
#pragma unroll
        for (int d = 0; d < 32; d++) s = fmaf(qr[d], ks[j][d], s);
        float e = __expf(s);          // logits are O(1); no max needed in fp32
        sum += e;
#pragma unroll
        for (int d = 0; d < 32; d++) acc[d] = fmaf(e, vs[j][d], acc[d]);
    }
    float inv = 1.f / sum;
    float* orow = out + ((size_t)bw * 64 + t) * 256 + h * 32;
#pragma unroll
    for (int d = 0; d < 32; d++) orow[d] = acc[d] * inv;
}

// ---------------- bf16 tensor-core NT GEMM, 128x128x32, fused epilogues -----
// MODE 0: QKV      (bias, store [r*768+c])
// MODE 1: LEPE     (shifted/masked A gather within window; C += acc + bias)
// MODE 2: PROJ     (bias; reverse shift; C[perm] = extra[perm] + acc)
// MODE 3: FC1+GELU
// MODE 4: FC2 + residual
__device__ __forceinline__ void ldmx4(uint32_t& r0, uint32_t& r1, uint32_t& r2, uint32_t& r3,
                                      const __nv_bfloat16* p) {
    uint32_t addr = (uint32_t)__cvta_generic_to_shared(p);
    asm volatile("ldmatrix.sync.aligned.m8n8.x4.shared.b16 {%0,%1,%2,%3}, [%4];"
                 : "=r"(r0), "=r"(r1), "=r"(r2), "=r"(r3) : "r"(addr));
}
__device__ __forceinline__ void mma16816(float* c, const uint32_t* a, const uint32_t* b) {
    asm volatile(
        "mma.sync.aligned.m16n8k16.row.col.f32.bf16.bf16.f32 "
        "{%0,%1,%2,%3}, {%4,%5,%6,%7}, {%8,%9}, {%0,%1,%2,%3};"
        : "+f"(c[0]), "+f"(c[1]), "+f"(c[2]), "+f"(c[3])
        : "r"(a[0]), "r"(a[1]), "r"(a[2]), "r"(a[3]), "r"(b[0]), "r"(b[1]));
}

template <int MODE>
__global__ __launch_bounds__(256) void bgemm_kernel(
    const float* __restrict__ A, const __nv_bfloat16* __restrict__ W,
    const float* __restrict__ bias, float* __restrict__ Cout,
    const float* __restrict__ extra, int Kin) {
    __shared__ __nv_bfloat16 As[128][40];
    __shared__ __nv_bfloat16 Bs[128][40];

    const int tid  = threadIdx.x;
    const int lane = tid & 31;
    const int warp = tid >> 5;
    const int wm   = warp >> 2;      // 0..1
    const int wn   = warp & 3;       // 0..3
    const int m0 = blockIdx.y * 128;
    const int n0 = blockIdx.x * 128;

    float c[4][4][4];
#pragma unroll
    for (int i = 0; i < 4; i++)
#pragma unroll
        for (int j = 0; j < 4; j++)
#pragma unroll
            for (int r = 0; r < 4; r++) c[i][j][r] = 0.f;

    for (int k0 = 0; k0 < Kin; k0 += 32) {
        // A tile: 128x32 fp32 -> bf16
#pragma unroll
        for (int l = 0; l < 4; l++) {
            int f = tid + l * 256;
            int row = f >> 3, c4 = (f & 7) * 4;
            float4 av;
            if (MODE == 1) {
                int d = (k0 >> 8) - 1;
                int R = m0 + row;
                int w = R & 63;
                if ((unsigned)(w + d) < 64u)
                    av = *reinterpret_cast<const float4*>(
                        A + (size_t)(R + d) * 768 + ((k0 + c4) & 255));
                else
                    av = make_float4(0.f, 0.f, 0.f, 0.f);
            } else {
                av = *reinterpret_cast<const float4*>(A + (size_t)(m0 + row) * Kin + k0 + c4);
            }
            __nv_bfloat162 p0 = __floats2bfloat162_rn(av.x, av.y);
            __nv_bfloat162 p1 = __floats2bfloat162_rn(av.z, av.w);
            uint2 pk = make_uint2(*reinterpret_cast<uint32_t*>(&p0),
                                  *reinterpret_cast<uint32_t*>(&p1));
            *reinterpret_cast<uint2*>(&As[row][c4]) = pk;
        }
        // B tile: 128x32 bf16 direct
#pragma unroll
        for (int l = 0; l < 2; l++) {
            int f = tid + l * 256;
            int row = f >> 2, c8 = (f & 3) * 8;
            uint4 wv = *reinterpret_cast<const uint4*>(W + (size_t)(n0 + row) * Kin + k0 + c8);
            *reinterpret_cast<uint4*>(&Bs[row][c8]) = wv;
        }
        __syncthreads();

#pragma unroll
        for (int ks = 0; ks < 2; ks++) {
            const int kk = ks * 16;
            uint32_t a[4][4], b[4][2];
#pragma unroll
            for (int i = 0; i < 4; i++) {
                int row = wm * 64 + i * 16 + (lane & 15);
                int col = kk + ((lane >> 4) << 3);
                ldmx4(a[i][0], a[i][1], a[i][2], a[i][3], &As[row][col]);
            }
#pragma unroll
            for (int jj = 0; jj < 2; jj++) {
                int row = wn * 32 + jj * 16 + (lane & 7) + ((lane >> 4) << 3);
                int col = kk + (((lane >> 3) & 1) << 3);
                ldmx4(b[2 * jj][0], b[2 * jj][1], b[2 * jj + 1][0], b[2 * jj + 1][1],
                      &Bs[row][col]);
            }
#pragma unroll
            for (int i = 0; i < 4; i++)
#pragma unroll
                for (int j = 0; j < 4; j++) mma16816(c[i][j], a[i], b[j]);
        }
        __syncthreads();
    }

    // epilogue
#pragma unroll
    for (int i = 0; i < 4; i++) {
        int r_base = m0 + wm * 64 + i * 16 + (lane >> 2);
#pragma unroll
        for (int j = 0; j < 4; j++) {
            int col = n0 + wn * 32 + j * 8 + (lane & 3) * 2;
            float2 bv = *reinterpret_cast<const float2*>(bias + col);
#pragma unroll
            for (int hh = 0; hh < 2; hh++) {
                int r = r_base + hh * 8;
                float v0 = c[i][j][hh * 2 + 0] + bv.x;
                float v1 = c[i][j][hh * 2 + 1] + bv.y;
                if (MODE == 0) {
                    *reinterpret_cast<float2*>(Cout + (size_t)r * 768 + col) =
                        make_float2(v0, v1);
                } else if (MODE == 1) {
                    size_t o = (size_t)r * 256 + col;
                    float2 e = *reinterpret_cast<const float2*>(Cout + o);
                    *reinterpret_cast<float2*>(Cout + o) = make_float2(e.x + v0, e.y + v1);
                } else if (MODE == 2) {
                    int b = r >> 12, n = r & 4095;
                    int n2 = (n + SH) & 4095;
                    size_t o = ((size_t)((b << 12) | n2)) * 256 + col;
                    float2 e = *reinterpret_cast<const float2*>(extra + o);
                    *reinterpret_cast<float2*>(Cout + o) = make_float2(e.x + v0, e.y + v1);
                } else if (MODE == 3) {
                    float g0 = 0.5f * v0 * (1.f + erff(v0 * 0.70710678118654752f));
                    float g1 = 0.5f * v1 * (1.f + erff(v1 * 0.70710678118654752f));
                    *reinterpret_cast<float2*>(Cout + (size_t)r * 1024 + col) =
                        make_float2(g0, g1);
                } else {
                    size_t o = (size_t)r * 256 + col;
                    float2 e = *reinterpret_cast<const float2*>(extra + o);
                    *reinterpret_cast<float2*>(Cout + o) = make_float2(v0 + e.x, v1 + e.y);
                }
            }
        }
    }
}

// ---------------- launch ----------------
extern "C" void kernel_launch(void* const* d_in, const int* in_sizes, int n_in,
                              void* d_out, int out_size) {
    const float* x     = (const float*)d_in[0];
    const float* mask  = (const float*)d_in[1];
    const float* n1w   = (const float*)d_in[2];
    const float* n1b   = (const float*)d_in[3];
    const float* qkvw  = (const float*)d_in[4];
    const float* qkvb  = (const float*)d_in[5];
    const float* posw  = (const float*)d_in[6];
    const float* posb  = (const float*)d_in[7];
    const float* projw = (const float*)d_in[8];
    const float* projb = (const float*)d_in[9];
    const float* n2w   = (const float*)d_in[10];
    const float* n2b   = (const float*)d_in[11];
    const float* fc1w  = (const float*)d_in[12];
    const float* fc1b  = (const float*)d_in[13];
    const float* fc2w  = (const float*)d_in[14];
    const float* fc2b  = (const float*)d_in[15];
    float* out = (float*)d_out;

    float *hs, *qkv, *attn, *x1, *m1;
    __nv_bfloat16* wbf;
    cudaGetSymbolAddress((void**)&hs,   g_hs);
    cudaGetSymbolAddress((void**)&qkv,  g_qkv);
    cudaGetSymbolAddress((void**)&attn, g_attn);
    cudaGetSymbolAddress((void**)&x1,   g_x1);
    cudaGetSymbolAddress((void**)&m1,   g_m1);
    cudaGetSymbolAddress((void**)&wbf,  g_wbf);

    // weight conversions (bf16)
    cvt_kernel<<<768, 256>>>(qkvw,  wbf + OFF_QKVW, 196608);
    posw_kernel<<<768, 256>>>(posw, wbf + OFF_LEPE);
    cvt_kernel<<<256, 256>>>(projw, wbf + OFF_PROJ, 65536);
    cvt_kernel<<<1024, 256>>>(fc1w, wbf + OFF_FC1, 262144);
    cvt_kernel<<<1024, 256>>>(fc2w, wbf + OFF_FC2, 262144);

    // LN1 fused with cyclic shift
    ln_kernel<<<ROWS, 64>>>(x, n1w, n1b, hs, SH);
    // QKV projection
    bgemm_kernel<0><<<dim3(6, ROWS / 128), 256>>>(hs, wbf + OFF_QKVW, qkvb, qkv, nullptr, 256);
    // windowed attention
    attn_kernel<<<BW * H_, 64>>>(qkv, mask, attn);
    // LePE conv as masked-gather GEMM, accumulated into attn output
    bgemm_kernel<1><<<dim3(2, ROWS / 128), 256>>>(qkv + 512, wbf + OFF_LEPE, posb, attn, nullptr, 768);
    // proj + reverse shift + first residual -> x1
    bgemm_kernel<2><<<dim3(2, ROWS / 128), 256>>>(attn, wbf + OFF_PROJ, projb, x1, x, 256);
    // LN2 (no shift)
    ln_kernel<<<ROWS, 64>>>(x1, n2w, n2b, hs, 0);
    // FC1 + exact GELU
    bgemm_kernel<3><<<dim3(8, ROWS / 128), 256>>>(hs, wbf + OFF_FC1, fc1b, m1, nullptr, 256);
    // FC2 + second residual -> output
    bgemm_kernel<4><<<dim3(2, ROWS / 128), 256>>>(m1, wbf + OFF_FC2, fc2b, out, x1, 1024);
}

// round 4
// speedup vs baseline: 2.8112x; 1.0154x over previous
#include <cuda_runtime.h>
#include <cuda_bf16.h>
#include <math.h>
#include <stdint.h>

// ---------------- problem constants ----------------
namespace {
constexpr int B_    = 32;
constexpr int NSEQ  = 4096;
constexpr int C     = 256;
constexpr int SH    = 32;
constexpr int H_    = 8;
constexpr int NWIN  = 64;
constexpr int ROWS  = B_ * NSEQ;          // 131072
constexpr int BW    = B_ * NWIN;          // 2048 windows
constexpr int HID   = 1024;
constexpr float SCALE = 0.17677669529663687f;  // 32^-0.5

constexpr size_t OFF_QKVW = 0;                       // 768*256
constexpr size_t OFF_LEPE = 196608;                  // 256*768
constexpr size_t OFF_PROJ = 393216;                  // 256*256
constexpr size_t OFF_FC1  = 458752;                  // 1024*256
constexpr size_t OFF_FC2  = 720896;                  // 256*1024
constexpr size_t WBF_TOT  = 983040;
}

// ---------------- scratch (device globals; allocation-free) ----------------
__device__ __nv_bfloat16 g_hs  [(size_t)ROWS * C];        // LN1/LN2 out (bf16)
__device__ __nv_bfloat16 g_qkv [(size_t)ROWS * 3 * C];    // qkv (bf16)
__device__ __nv_bfloat16 g_attn[(size_t)ROWS * C];        // attn out (+LePE RMW, bf16)
__device__ float         g_x1  [(size_t)ROWS * C];        // first residual (fp32)
__device__ __nv_bfloat16 g_m1  [(size_t)ROWS * HID];      // FFN hidden (bf16)
__device__ __nv_bfloat16 g_wbf[WBF_TOT];

// ---------------- weight conversion ----------------
__global__ void cvt_kernel(const float* __restrict__ src, __nv_bfloat16* __restrict__ dst, int n) {
    int i = blockIdx.x * 256 + threadIdx.x;
    if (i < n) dst[i] = __float2bfloat16(src[i]);
}

// pos_w [o][i][t] -> bf16 [o][t*256+i]
__global__ void posw_kernel(const float* __restrict__ pw, __nv_bfloat16* __restrict__ dst) {
    int idx = blockIdx.x * 256 + threadIdx.x;      // 196608
    int o = idx / 768, kk = idx % 768;
    int t = kk >> 8, i = kk & 255;
    dst[idx] = __float2bfloat16(pw[(size_t)o * 768 + i * 3 + t]);
}

// ---------------- LayerNorm (optional cyclic-shift read), bf16 out ----------
__global__ __launch_bounds__(64) void ln_kernel(const float* __restrict__ x,
                                                const float* __restrict__ w,
                                                const float* __restrict__ bvec,
                                                __nv_bfloat16* __restrict__ out, int shift) {
    int row = blockIdx.x;
    int b = row >> 12, n = row & 4095;
    int src = (b << 12) | ((n + shift) & 4095);
    const float4* xin = reinterpret_cast<const float4*>(x + (size_t)src * C);
    int t = threadIdx.x;
    float4 v = xin[t];
    float s = v.x + v.y + v.z + v.w;
    float q = v.x * v.x + v.y * v.y + v.z * v.z + v.w * v.w;
#pragma unroll
    for (int o = 16; o > 0; o >>= 1) {
        s += __shfl_xor_sync(0xffffffffu, s, o);
        q += __shfl_xor_sync(0xffffffffu, q, o);
    }
    __shared__ float sh[4];
    if ((t & 31) == 0) { sh[t >> 5] = s; sh[2 + (t >> 5)] = q; }
    __syncthreads();
    s = sh[0] + sh[1]; q = sh[2] + sh[3];
    float mean = s * (1.0f / C);
    float var  = q * (1.0f / C) - mean * mean;
    float rstd = rsqrtf(var + 1e-5f);
    float4 wv = reinterpret_cast<const float4*>(w)[t];
    float4 bv = reinterpret_cast<const float4*>(bvec)[t];
    __nv_bfloat162 o0 = __floats2bfloat162_rn((v.x - mean) * rstd * wv.x + bv.x,
                                              (v.y - mean) * rstd * wv.y + bv.y);
    __nv_bfloat162 o1 = __floats2bfloat162_rn((v.z - mean) * rstd * wv.z + bv.z,
                                              (v.w - mean) * rstd * wv.w + bv.w);
    uint2 pk = make_uint2(*reinterpret_cast<uint32_t*>(&o0), *reinterpret_cast<uint32_t*>(&o1));
    reinterpret_cast<uint2*>(out + (size_t)row * C)[t] = pk;
}

// ---------------- windowed attention (bf16 in/out, fp32 math) --------------
__global__ __launch_bounds__(64) void attn_kernel(const __nv_bfloat16* __restrict__ qkv,
                                                  const float* __restrict__ mask,
                                                  __nv_bfloat16* __restrict__ out) {
    int wh = blockIdx.x;
    int bw = wh >> 3;          // window id
    int h  = wh & 7;           // head
    int wIdx = bw & 63;        // window index within sequence
    int t = threadIdx.x;       // query row

    __shared__ float ks[64][33];
    __shared__ float vs[64][33];

    const __nv_bfloat16* rowp = qkv + ((size_t)bw * 64 + t) * 768 + h * 32;
    float qr[32];
#pragma unroll
    for (int c = 0; c < 4; c++) {
        uint4 kq = *reinterpret_cast<const uint4*>(rowp + 256 + c * 8);
        uint4 vq = *reinterpret_cast<const uint4*>(rowp + 512 + c * 8);
        uint4 qq = *reinterpret_cast<const uint4*>(rowp + c * 8);
        const uint32_t* kw = &kq.x;
        const uint32_t* vw = &vq.x;
        const uint32_t* qw = &qq.x;
#pragma unroll
        for (int u = 0; u < 4; u++) {
            float2 kf = __bfloat1622float2(*reinterpret_cast<const __nv_bfloat162*>(&kw[u]));
            float2 vf = __bfloat1622float2(*reinterpret_cast<const __nv_bfloat162*>(&vw[u]));
            float2 qf = __bfloat1622float2(*reinterpret_cast<const __nv_bfloat162*>(&qw[u]));
            ks[t][c * 8 + u * 2 + 0] = kf.x; ks[t][c * 8 + u * 2 + 1] = kf.y;
            vs[t][c * 8 + u * 2 + 0] = vf.x; vs[t][c * 8 + u * 2 + 1] = vf.y;
            qr[c * 8 + u * 2 + 0] = qf.x * SCALE; qr[c * 8 + u * 2 + 1] = qf.y * SCALE;
        }
    }
    __syncthreads();

    const float* mrow = mask + ((size_t)wIdx * 64 + t) * 64;
    float sum = 0.f;
    float acc[32];
#pragma unroll
    for (int d = 0; d < 32; d++) acc[d] = 0.f;
#pragma unroll 2
    for (int j = 0; j < 64; j++) {
        float s = mrow[j];
#pragma unroll
        for (int d = 0; d < 32; d++) s = fmaf(qr[d], ks[j][d], s);
        float e = __expf(s);          // logits O(1) in fp32; no max needed
        sum += e;
#pragma unroll
        for (int d = 0; d < 32; d++) acc[d] = fmaf(e, vs[j][d], acc[d]);
    }
    float inv = 1.f / sum;
    __nv_bfloat16* orow = out + ((size_t)bw * 64 + t) * 256 + h * 32;
#pragma unroll
    for (int u = 0; u < 16; u++) {
        __nv_bfloat162 p = __floats2bfloat162_rn(acc[2 * u] * inv, acc[2 * u + 1] * inv);
        *reinterpret_cast<uint32_t*>(orow + 2 * u) = *reinterpret_cast<uint32_t*>(&p);
    }
}

// ---------------- bf16 tensor-core NT GEMM, 128x128x32, fused epilogues -----
// MODE 0: QKV      (bias; bf16 store [r*768+c])
// MODE 1: LEPE     (shifted/masked bf16 A gather; bf16 RMW  C += acc + bias)
// MODE 2: PROJ     (bias; reverse shift; fp32 C[perm] = extra[perm] + acc)
// MODE 3: FC1+GELU (bias; bf16 store)
// MODE 4: FC2      (bias + fp32 residual; fp32 store)
__device__ __forceinline__ void ldmx4(uint32_t& r0, uint32_t& r1, uint32_t& r2, uint32_t& r3,
                                      const __nv_bfloat16* p) {
    uint32_t addr = (uint32_t)__cvta_generic_to_shared(p);
    asm volatile("ldmatrix.sync.aligned.m8n8.x4.shared.b16 {%0,%1,%2,%3}, [%4];"
                 : "=r"(r0), "=r"(r1), "=r"(r2), "=r"(r3) : "r"(addr));
}
__device__ __forceinline__ void mma16816(float* c, const uint32_t* a, const uint32_t* b) {
    asm volatile(
        "mma.sync.aligned.m16n8k16.row.col.f32.bf16.bf16.f32 "
        "{%0,%1,%2,%3}, {%4,%5,%6,%7}, {%8,%9}, {%0,%1,%2,%3};"
        : "+f"(c[0]), "+f"(c[1]), "+f"(c[2]), "+f"(c[3])
        : "r"(a[0]), "r"(a[1]), "r"(a[2]), "r"(a[3]), "r"(b[0]), "r"(b[1]));
}

template <int MODE>
__global__ __launch_bounds__(256) void bgemm_kernel(
    const __nv_bfloat16* __restrict__ A, const __nv_bfloat16* __restrict__ W,
    const float* __restrict__ bias, void* __restrict__ CoutV,
    const float* __restrict__ extra, int Kin) {
    __shared__ __nv_bfloat16 As[128][40];
    __shared__ __nv_bfloat16 Bs[128][40];

    const int tid  = threadIdx.x;
    const int lane = tid & 31;
    const int warp = tid >> 5;
    const int wm   = warp >> 2;      // 0..1
    const int wn   = warp & 3;       // 0..3
    const int m0 = blockIdx.y * 128;
    const int n0 = blockIdx.x * 128;

    float c[4][4][4];
#pragma unroll
    for (int i = 0; i < 4; i++)
#pragma unroll
        for (int j = 0; j < 4; j++)
#pragma unroll
            for (int r = 0; r < 4; r++) c[i][j][r] = 0.f;

    for (int k0 = 0; k0 < Kin; k0 += 32) {
        // A tile: 128x32 bf16
#pragma unroll
        for (int l = 0; l < 2; l++) {
            int f = tid + l * 256;
            int row = f >> 2, c8 = (f & 3) * 8;
            uint4 av;
            if (MODE == 1) {
                int d = (k0 >> 8) - 1;           // tap shift: -1,0,+1
                int R = m0 + row;
                int w = R & 63;
                if ((unsigned)(w + d) < 64u)
                    av = *reinterpret_cast<const uint4*>(
                        A + (size_t)(R + d) * 768 + ((k0 + c8) & 255));
                else
                    av = make_uint4(0u, 0u, 0u, 0u);
            } else {
                av = *reinterpret_cast<const uint4*>(A + (size_t)(m0 + row) * Kin + k0 + c8);
            }
            *reinterpret_cast<uint4*>(&As[row][c8]) = av;
            uint4 wv = *reinterpret_cast<const uint4*>(W + (size_t)(n0 + row) * Kin + k0 + c8);
            *reinterpret_cast<uint4*>(&Bs[row][c8]) = wv;
        }
        __syncthreads();

#pragma unroll
        for (int ks = 0; ks < 2; ks++) {
            const int kk = ks * 16;
            uint32_t a[4][4], b[4][2];
#pragma unroll
            for (int i = 0; i < 4; i++) {
                int row = wm * 64 + i * 16 + (lane & 15);
                int col = kk + ((lane >> 4) << 3);
                ldmx4(a[i][0], a[i][1], a[i][2], a[i][3], &As[row][col]);
            }
#pragma unroll
            for (int jj = 0; jj < 2; jj++) {
                int row = wn * 32 + jj * 16 + (lane & 7) + ((lane >> 4) << 3);
                int col = kk + (((lane >> 3) & 1) << 3);
                ldmx4(b[2 * jj][0], b[2 * jj][1], b[2 * jj + 1][0], b[2 * jj + 1][1],
                      &Bs[row][col]);
            }
#pragma unroll
            for (int i = 0; i < 4; i++)
#pragma unroll
                for (int j = 0; j < 4; j++) mma16816(c[i][j], a[i], b[j]);
        }
        __syncthreads();
    }

    // epilogue
#pragma unroll
    for (int i = 0; i < 4; i++) {
        int r_base = m0 + wm * 64 + i * 16 + (lane >> 2);
#pragma unroll
        for (int j = 0; j < 4; j++) {
            int col = n0 + wn * 32 + j * 8 + (lane & 3) * 2;
            float2 bv = *reinterpret_cast<const float2*>(bias + col);
#pragma unroll
            for (int hh = 0; hh < 2; hh++) {
                int r = r_base + hh * 8;
                float v0 = c[i][j][hh * 2 + 0] + bv.x;
                float v1 = c[i][j][hh * 2 + 1] + bv.y;
                if (MODE == 0) {
                    __nv_bfloat16* Cb = (__nv_bfloat16*)CoutV;
                    __nv_bfloat162 p = __floats2bfloat162_rn(v0, v1);
                    *reinterpret_cast<uint32_t*>(Cb + (size_t)r * 768 + col) =
                        *reinterpret_cast<uint32_t*>(&p);
                } else if (MODE == 1) {
                    __nv_bfloat16* Cb = (__nv_bfloat16*)CoutV;
                    size_t o = (size_t)r * 256 + col;
                    uint32_t old = *reinterpret_cast<uint32_t*>(Cb + o);
                    float2 e = __bfloat1622float2(*reinterpret_cast<__nv_bfloat162*>(&old));
                    __nv_bfloat162 p = __floats2bfloat162_rn(e.x + v0, e.y + v1);
                    *reinterpret_cast<uint32_t*>(Cb + o) = *reinterpret_cast<uint32_t*>(&p);
                } else if (MODE == 2) {
                    float* Cf = (float*)CoutV;
                    int b = r >> 12, n = r & 4095;
                    int n2 = (n + SH) & 4095;
                    size_t o = ((size_t)((b << 12) | n2)) * 256 + col;
                    float2 e = *reinterpret_cast<const float2*>(extra + o);
                    *reinterpret_cast<float2*>(Cf + o) = make_float2(e.x + v0, e.y + v1);
                } else if (MODE == 3) {
                    __nv_bfloat16* Cb = (__nv_bfloat16*)CoutV;
                    float g0 = 0.5f * v0 * (1.f + erff(v0 * 0.70710678118654752f));
                    float g1 = 0.5f * v1 * (1.f + erff(v1 * 0.70710678118654752f));
                    __nv_bfloat162 p = __floats2bfloat162_rn(g0, g1);
                    *reinterpret_cast<uint32_t*>(Cb + (size_t)r * 1024 + col) =
                        *reinterpret_cast<uint32_t*>(&p);
                } else {
                    float* Cf = (float*)CoutV;
                    size_t o = (size_t)r * 256 + col;
                    float2 e = *reinterpret_cast<const float2*>(extra + o);
                    *reinterpret_cast<float2*>(Cf + o) = make_float2(v0 + e.x, v1 + e.y);
                }
            }
        }
    }
}

// ---------------- launch ----------------
extern "C" void kernel_launch(void* const* d_in, const int* in_sizes, int n_in,
                              void* d_out, int out_size) {
    const float* x     = (const float*)d_in[0];
    const float* mask  = (const float*)d_in[1];
    const float* n1w   = (const float*)d_in[2];
    const float* n1b   = (const float*)d_in[3];
    const float* qkvw  = (const float*)d_in[4];
    const float* qkvb  = (const float*)d_in[5];
    const float* posw  = (const float*)d_in[6];
    const float* posb  = (const float*)d_in[7];
    const float* projw = (const float*)d_in[8];
    const float* projb = (const float*)d_in[9];
    const float* n2w   = (const float*)d_in[10];
    const float* n2b   = (const float*)d_in[11];
    const float* fc1w  = (const float*)d_in[12];
    const float* fc1b  = (const float*)d_in[13];
    const float* fc2w  = (const float*)d_in[14];
    const float* fc2b  = (const float*)d_in[15];
    float* out = (float*)d_out;

    __nv_bfloat16 *hs, *qkv, *attn, *m1, *wbf;
    float *x1;
    cudaGetSymbolAddress((void**)&hs,   g_hs);
    cudaGetSymbolAddress((void**)&qkv,  g_qkv);
    cudaGetSymbolAddress((void**)&attn, g_attn);
    cudaGetSymbolAddress((void**)&x1,   g_x1);
    cudaGetSymbolAddress((void**)&m1,   g_m1);
    cudaGetSymbolAddress((void**)&wbf,  g_wbf);

    // weight conversions (bf16)
    cvt_kernel<<<768, 256>>>(qkvw,  wbf + OFF_QKVW, 196608);
    posw_kernel<<<768, 256>>>(posw, wbf + OFF_LEPE);
    cvt_kernel<<<256, 256>>>(projw, wbf + OFF_PROJ, 65536);
    cvt_kernel<<<1024, 256>>>(fc1w, wbf + OFF_FC1, 262144);
    cvt_kernel<<<1024, 256>>>(fc2w, wbf + OFF_FC2, 262144);

    // LN1 fused with cyclic shift
    ln_kernel<<<ROWS, 64>>>(x, n1w, n1b, hs, SH);
    // QKV projection
    bgemm_kernel<0><<<dim3(6, ROWS / 128), 256>>>(hs, wbf + OFF_QKVW, qkvb, qkv, nullptr, 256);
    // windowed attention
    attn_kernel<<<BW * H_, 64>>>(qkv, mask, attn);
    // LePE conv as masked-gather GEMM, accumulated into attn output (bf16 RMW)
    bgemm_kernel<1><<<dim3(2, ROWS / 128), 256>>>(qkv + 512, wbf + OFF_LEPE, posb, attn, nullptr, 768);
    // proj + reverse shift + first residual -> x1 (fp32)
    bgemm_kernel<2><<<dim3(2, ROWS / 128), 256>>>(attn, wbf + OFF_PROJ, projb, x1, x, 256);
    // LN2 (no shift)
    ln_kernel<<<ROWS, 64>>>(x1, n2w, n2b, hs, 0);
    // FC1 + exact GELU (bf16 out)
    bgemm_kernel<3><<<dim3(8, ROWS / 128), 256>>>(hs, wbf + OFF_FC1, fc1b, m1, nullptr, 256);
    // FC2 + second residual -> output (fp32)
    bgemm_kernel<4><<<dim3(2, ROWS / 128), 256>>>(m1, wbf + OFF_FC2, fc2b, out, x1, 1024);
}

// round 6
// speedup vs baseline: 2.9309x; 1.0426x over previous
#include <cuda_runtime.h>
#include <cuda_bf16.h>
#include <math.h>
#include <stdint.h>

// ---------------- problem constants ----------------
namespace {
constexpr int B_    = 32;
constexpr int NSEQ  = 4096;
constexpr int C     = 256;
constexpr int SH    = 32;
constexpr int H_    = 8;
constexpr int ROWS  = B_ * NSEQ;          // 131072
constexpr int BW    = B_ * 64;            // 2048 windows
constexpr int HID   = 1024;
constexpr float SCALE = 0.17677669529663687f;  // 32^-0.5

constexpr size_t OFF_QKVW = 0;                       // 768*256
constexpr size_t OFF_LEPE = 196608;                  // 256*768
constexpr size_t OFF_PROJ = 393216;                  // 256*256
constexpr size_t OFF_FC1  = 458752;                  // 1024*256
constexpr size_t OFF_FC2  = 720896;                  // 256*1024
constexpr size_t WBF_TOT  = 983040;

constexpr int LDS_H = 72;                 // halfwords per smem row (144 B)
constexpr int TILE_HW = 128 * LDS_H;      // halfwords per tile
constexpr int SMEM_DYN = 2 * 2 * TILE_HW * 2;  // 73728 B
}

// ---------------- scratch ----------------
__device__ __nv_bfloat16 g_hs  [(size_t)ROWS * C];
__device__ __nv_bfloat16 g_qkv [(size_t)ROWS * 3 * C];
__device__ __nv_bfloat16 g_attn[(size_t)ROWS * C];
__device__ float         g_x1  [(size_t)ROWS * C];
__device__ __nv_bfloat16 g_m1  [(size_t)ROWS * HID];
__device__ __nv_bfloat16 g_wbf[WBF_TOT];

// ---------------- helpers ----------------
__device__ __forceinline__ uint32_t pack_bf2(float a, float b) {
    __nv_bfloat162 p = __floats2bfloat162_rn(a, b);
    return *reinterpret_cast<uint32_t*>(&p);
}
__device__ __forceinline__ void cpa16(uint32_t dst, const void* src) {
    asm volatile("cp.async.cg.shared.global [%0], [%1], 16;" :: "r"(dst), "l"(src));
}
__device__ __forceinline__ void cpa16_pred(uint32_t dst, const void* src, bool v) {
    int sz = v ? 16 : 0;
    asm volatile("cp.async.cg.shared.global [%0], [%1], 16, %2;"
                 :: "r"(dst), "l"(src), "r"(sz));
}
__device__ __forceinline__ void ldmx4(uint32_t& r0, uint32_t& r1, uint32_t& r2, uint32_t& r3,
                                      uint32_t addr) {
    asm volatile("ldmatrix.sync.aligned.m8n8.x4.shared.b16 {%0,%1,%2,%3}, [%4];"
                 : "=r"(r0), "=r"(r1), "=r"(r2), "=r"(r3) : "r"(addr));
}
__device__ __forceinline__ void mma16816(float* c, const uint32_t* a, const uint32_t* b) {
    asm volatile(
        "mma.sync.aligned.m16n8k16.row.col.f32.bf16.bf16.f32 "
        "{%0,%1,%2,%3}, {%4,%5,%6,%7}, {%8,%9}, {%0,%1,%2,%3};"
        : "+f"(c[0]), "+f"(c[1]), "+f"(c[2]), "+f"(c[3])
        : "r"(a[0]), "r"(a[1]), "r"(a[2]), "r"(a[3]), "r"(b[0]), "r"(b[1]));
}

// ---------------- weight conversion ----------------
__global__ void cvt_kernel(const float* __restrict__ src, __nv_bfloat16* __restrict__ dst, int n) {
    int i = blockIdx.x * 256 + threadIdx.x;
    if (i < n) dst[i] = __float2bfloat16(src[i]);
}
__global__ void posw_kernel(const float* __restrict__ pw, __nv_bfloat16* __restrict__ dst) {
    int idx = blockIdx.x * 256 + threadIdx.x;      // 196608
    int o = idx / 768, kk = idx % 768;
    int t = kk >> 8, i = kk & 255;
    dst[idx] = __float2bfloat16(pw[(size_t)o * 768 + i * 3 + t]);
}

// ---------------- LayerNorm (optional cyclic-shift read), bf16 out ----------
__global__ __launch_bounds__(64) void ln_kernel(const float* __restrict__ x,
                                                const float* __restrict__ w,
                                                const float* __restrict__ bvec,
                                                __nv_bfloat16* __restrict__ out, int shift) {
    int row = blockIdx.x;
    int b = row >> 12, n = row & 4095;
    int src = (b << 12) | ((n + shift) & 4095);
    const float4* xin = reinterpret_cast<const float4*>(x + (size_t)src * C);
    int t = threadIdx.x;
    float4 v = xin[t];
    float s = v.x + v.y + v.z + v.w;
    float q = v.x * v.x + v.y * v.y + v.z * v.z + v.w * v.w;
#pragma unroll
    for (int o = 16; o > 0; o >>= 1) {
        s += __shfl_xor_sync(0xffffffffu, s, o);
        q += __shfl_xor_sync(0xffffffffu, q, o);
    }
    __shared__ float sh[4];
    if ((t & 31) == 0) { sh[t >> 5] = s; sh[2 + (t >> 5)] = q; }
    __syncthreads();
    s = sh[0] + sh[1]; q = sh[2] + sh[3];
    float mean = s * (1.0f / C);
    float var  = q * (1.0f / C) - mean * mean;
    float rstd = rsqrtf(var + 1e-5f);
    float4 wv = reinterpret_cast<const float4*>(w)[t];
    float4 bv = reinterpret_cast<const float4*>(bvec)[t];
    uint2 pk = make_uint2(pack_bf2((v.x - mean) * rstd * wv.x + bv.x,
                                   (v.y - mean) * rstd * wv.y + bv.y),
                          pack_bf2((v.z - mean) * rstd * wv.z + bv.z,
                                   (v.w - mean) * rstd * wv.w + bv.w));
    reinterpret_cast<uint2*>(out + (size_t)row * C)[t] = pk;
}

// ---------------- windowed attention (bf16 in/out, fp32 math) --------------
__global__ __launch_bounds__(64) void attn_kernel(const __nv_bfloat16* __restrict__ qkv,
                                                  const float* __restrict__ mask,
                                                  __nv_bfloat16* __restrict__ out) {
    int wh = blockIdx.x;
    int bw = wh >> 3;
    int h  = wh & 7;
    int wIdx = bw & 63;
    int t = threadIdx.x;

    __shared__ float ks[64][33];
    __shared__ float vs[64][33];

    const __nv_bfloat16* rowp = qkv + ((size_t)bw * 64 + t) * 768 + h * 32;
    float qr[32];
#pragma unroll
    for (int c = 0; c < 4; c++) {
        uint4 kq = *reinterpret_cast<const uint4*>(rowp + 256 + c * 8);
        uint4 vq = *reinterpret_cast<const uint4*>(rowp + 512 + c * 8);
        uint4 qq = *reinterpret_cast<const uint4*>(rowp + c * 8);
        const uint32_t* kw = &kq.x;
        const uint32_t* vw = &vq.x;
        const uint32_t* qw = &qq.x;
#pragma unroll
        for (int u = 0; u < 4; u++) {
            float2 kf = __bfloat1622float2(*reinterpret_cast<const __nv_bfloat162*>(&kw[u]));
            float2 vf = __bfloat1622float2(*reinterpret_cast<const __nv_bfloat162*>(&vw[u]));
            float2 qf = __bfloat1622float2(*reinterpret_cast<const __nv_bfloat162*>(&qw[u]));
            ks[t][c * 8 + u * 2 + 0] = kf.x; ks[t][c * 8 + u * 2 + 1] = kf.y;
            vs[t][c * 8 + u * 2 + 0] = vf.x; vs[t][c * 8 + u * 2 + 1] = vf.y;
            qr[c * 8 + u * 2 + 0] = qf.x * SCALE; qr[c * 8 + u * 2 + 1] = qf.y * SCALE;
        }
    }
    __syncthreads();

    const float* mrow = mask + ((size_t)wIdx * 64 + t) * 64;
    float sum = 0.f;
    float acc[32];
#pragma unroll
    for (int d = 0; d < 32; d++) acc[d] = 0.f;
#pragma unroll 2
    for (int j = 0; j < 64; j++) {
        float s = mrow[j];
#pragma unroll
        for (int d = 0; d < 32; d++) s = fmaf(qr[d], ks[j][d], s);
        float e = __expf(s);
        sum += e;
#pragma unroll
        for (int d = 0; d < 32; d++) acc[d] = fmaf(e, vs[j][d], acc[d]);
    }
    float inv = 1.f / sum;
    __nv_bfloat16* orow = out + ((size_t)bw * 64 + t) * 256 + h * 32;
#pragma unroll
    for (int u = 0; u < 16; u++) {
        *reinterpret_cast<uint32_t*>(orow + 2 * u) = pack_bf2(acc[2 * u] * inv, acc[2 * u + 1] * inv);
    }
}

// ---------------- pipelined bf16 mma.sync NT GEMM, 128x128 tile, BK=64 ------
// MODE 0: QKV (bf16, ld 768) | 1: LEPE (gather A, bf16 RMW) |
// 2: PROJ (fp32, reverse shift + residual) | 3: FC1+GELU (bf16, ld 1024) |
// 4: FC2 (fp32 + residual)
template <int MODE>
__global__ __launch_bounds__(256, 1) void bgemm_kernel(
    const __nv_bfloat16* __restrict__ A, const __nv_bfloat16* __restrict__ W,
    const float* __restrict__ bias, void* __restrict__ CoutV,
    const float* __restrict__ extra, int Kin) {
    extern __shared__ __nv_bfloat16 smem[];
    // layout: buf p: A tile at p*2*TILE_HW, B tile at p*2*TILE_HW + TILE_HW
    const int tid  = threadIdx.x;
    const int lane = tid & 31;
    const int warp = tid >> 5;
    const int wm   = warp >> 2;      // 0..1
    const int wn   = warp & 3;       // 0..3
    const int m0 = blockIdx.y * 128;
    const int n0 = blockIdx.x * 128;

    const uint32_t sbase = (uint32_t)__cvta_generic_to_shared(smem);
    const int nslab = Kin >> 6;

    // ---- loader: one BK=64 slab (A+B) into buffer p ----
    auto load_slab = [&](int s) {
        const int p = s & 1;
        const int k0 = s << 6;
        uint32_t a_s = sbase + p * (2 * TILE_HW * 2);
        uint32_t b_s = a_s + TILE_HW * 2;
        // 128 rows x 128 bytes per tile = 1024 chunks of 16B; 4 per thread per tile
#pragma unroll
        for (int i = 0; i < 4; i++) {
            int ch = tid + i * 256;
            int row = ch >> 3;
            int cb = (ch & 7) * 16;                 // byte col within 128B of data
            int colh = cb >> 1;                     // halfword col
            uint32_t doff = row * 144 + cb;         // padded row stride 144B
            if (MODE == 1) {
                int d = (k0 >> 8) - 1;
                int R = m0 + row;
                bool v = ((unsigned)((R & 63) + d) < 64u);
                const __nv_bfloat16* src =
                    v ? (A + (size_t)(R + d) * 768 + ((k0 + colh) & 255)) : A;
                cpa16_pred(a_s + doff, src, v);
            } else {
                cpa16(a_s + doff, A + (size_t)(m0 + row) * Kin + k0 + colh);
            }
            cpa16(b_s + doff, W + (size_t)(n0 + row) * Kin + k0 + colh);
        }
        asm volatile("cp.async.commit_group;" ::: "memory");
    };

    float c[4][4][4];
#pragma unroll
    for (int i = 0; i < 4; i++)
#pragma unroll
        for (int j = 0; j < 4; j++)
#pragma unroll
            for (int r = 0; r < 4; r++) c[i][j][r] = 0.f;

    load_slab(0);
    for (int s = 0; s < nslab; s++) {
        if (s + 1 < nslab) {
            load_slab(s + 1);
            asm volatile("cp.async.wait_group 1;" ::: "memory");
        } else {
            asm volatile("cp.async.wait_group 0;" ::: "memory");
        }
        __syncthreads();

        const int p = s & 1;
        uint32_t a_s = sbase + p * (2 * TILE_HW * 2);
        uint32_t b_s = a_s + TILE_HW * 2;
#pragma unroll
        for (int ks = 0; ks < 4; ks++) {
            const int kk = ks * 16;
            uint32_t a[4][4], b[4][2];
#pragma unroll
            for (int i = 0; i < 4; i++) {
                int row = wm * 64 + i * 16 + (lane & 15);
                int col = kk + ((lane >> 4) << 3);
                ldmx4(a[i][0], a[i][1], a[i][2], a[i][3], a_s + row * 144 + col * 2);
            }
#pragma unroll
            for (int jj = 0; jj < 2; jj++) {
                int row = wn * 32 + jj * 16 + (lane & 7) + ((lane >> 4) << 3);
                int col = kk + (((lane >> 3) & 1) << 3);
                ldmx4(b[2 * jj][0], b[2 * jj][1], b[2 * jj + 1][0], b[2 * jj + 1][1],
                      b_s + row * 144 + col * 2);
            }
#pragma unroll
            for (int i = 0; i < 4; i++)
#pragma unroll
                for (int j = 0; j < 4; j++) mma16816(c[i][j], a[i], b[j]);
        }
        __syncthreads();
    }

    // epilogue
#pragma unroll
    for (int i = 0; i < 4; i++) {
        int r_base = m0 + wm * 64 + i * 16 + (lane >> 2);
#pragma unroll
        for (int j = 0; j < 4; j++) {
            int col = n0 + wn * 32 + j * 8 + (lane & 3) * 2;
            float2 bv = *reinterpret_cast<const float2*>(bias + col);
#pragma unroll
            for (int hh = 0; hh < 2; hh++) {
                int r = r_base + hh * 8;
                float v0 = c[i][j][hh * 2 + 0] + bv.x;
                float v1 = c[i][j][hh * 2 + 1] + bv.y;
                if (MODE == 0) {
                    __nv_bfloat16* Cb = (__nv_bfloat16*)CoutV;
                    *reinterpret_cast<uint32_t*>(Cb + (size_t)r * 768 + col) = pack_bf2(v0, v1);
                } else if (MODE == 1) {
                    __nv_bfloat16* Cb = (__nv_bfloat16*)CoutV;
                    size_t o = (size_t)r * 256 + col;
                    uint32_t old = *reinterpret_cast<uint32_t*>(Cb + o);
                    float2 e = __bfloat1622float2(*reinterpret_cast<__nv_bfloat162*>(&old));
                    *reinterpret_cast<uint32_t*>(Cb + o) = pack_bf2(e.x + v0, e.y + v1);
                } else if (MODE == 2) {
                    float* Cf = (float*)CoutV;
                    int b = r >> 12, n = r & 4095;
                    int n2 = (n + SH) & 4095;
                    size_t o = ((size_t)((b << 12) | n2)) * 256 + col;
                    float2 e = *reinterpret_cast<const float2*>(extra + o);
                    *reinterpret_cast<float2*>(Cf + o) = make_float2(e.x + v0, e.y + v1);
                } else if (MODE == 3) {
                    __nv_bfloat16* Cb = (__nv_bfloat16*)CoutV;
                    float g0 = 0.5f * v0 * (1.f + erff(v0 * 0.70710678118654752f));
                    float g1 = 0.5f * v1 * (1.f + erff(v1 * 0.70710678118654752f));
                    *reinterpret_cast<uint32_t*>(Cb + (size_t)r * 1024 + col) = pack_bf2(g0, g1);
                } else {
                    float* Cf = (float*)CoutV;
                    size_t o = (size_t)r * 256 + col;
                    float2 e = *reinterpret_cast<const float2*>(extra + o);
                    *reinterpret_cast<float2*>(Cf + o) = make_float2(v0 + e.x, v1 + e.y);
                }
            }
        }
    }
}

// ---------------- launch ----------------
extern "C" void kernel_launch(void* const* d_in, const int* in_sizes, int n_in,
                              void* d_out, int out_size) {
    const float* x     = (const float*)d_in[0];
    const float* mask  = (const float*)d_in[1];
    const float* n1w   = (const float*)d_in[2];
    const float* n1b   = (const float*)d_in[3];
    const float* qkvw  = (const float*)d_in[4];
    const float* qkvb  = (const float*)d_in[5];
    const float* posw  = (const float*)d_in[6];
    const float* posb  = (const float*)d_in[7];
    const float* projw = (const float*)d_in[8];
    const float* projb = (const float*)d_in[9];
    const float* n2w   = (const float*)d_in[10];
    const float* n2b   = (const float*)d_in[11];
    const float* fc1w  = (const float*)d_in[12];
    const float* fc1b  = (const float*)d_in[13];
    const float* fc2w  = (const float*)d_in[14];
    const float* fc2b  = (const float*)d_in[15];
    float* out = (float*)d_out;

    __nv_bfloat16 *hs, *qkv, *attn, *m1, *wbf;
    float *x1;
    cudaGetSymbolAddress((void**)&hs,   g_hs);
    cudaGetSymbolAddress((void**)&qkv,  g_qkv);
    cudaGetSymbolAddress((void**)&attn, g_attn);
    cudaGetSymbolAddress((void**)&x1,   g_x1);
    cudaGetSymbolAddress((void**)&m1,   g_m1);
    cudaGetSymbolAddress((void**)&wbf,  g_wbf);

    static bool attr_done = false;
    if (!attr_done) {
        cudaFuncSetAttribute(bgemm_kernel<0>, cudaFuncAttributeMaxDynamicSharedMemorySize, SMEM_DYN);
        cudaFuncSetAttribute(bgemm_kernel<1>, cudaFuncAttributeMaxDynamicSharedMemorySize, SMEM_DYN);
        cudaFuncSetAttribute(bgemm_kernel<2>, cudaFuncAttributeMaxDynamicSharedMemorySize, SMEM_DYN);
        cudaFuncSetAttribute(bgemm_kernel<3>, cudaFuncAttributeMaxDynamicSharedMemorySize, SMEM_DYN);
        cudaFuncSetAttribute(bgemm_kernel<4>, cudaFuncAttributeMaxDynamicSharedMemorySize, SMEM_DYN);
        attr_done = true;
    }

    cvt_kernel<<<768, 256>>>(qkvw,  wbf + OFF_QKVW, 196608);
    posw_kernel<<<768, 256>>>(posw, wbf + OFF_LEPE);
    cvt_kernel<<<256, 256>>>(projw, wbf + OFF_PROJ, 65536);
    cvt_kernel<<<1024, 256>>>(fc1w, wbf + OFF_FC1, 262144);
    cvt_kernel<<<1024, 256>>>(fc2w, wbf + OFF_FC2, 262144);

    ln_kernel<<<ROWS, 64>>>(x, n1w, n1b, hs, SH);
    bgemm_kernel<0><<<dim3(6, ROWS / 128), 256, SMEM_DYN>>>(hs, wbf + OFF_QKVW, qkvb, qkv, nullptr, 256);
    attn_kernel<<<BW * H_, 64>>>(qkv, mask, attn);
    bgemm_kernel<1><<<dim3(2, ROWS / 128), 256, SMEM_DYN>>>(qkv + 512, wbf + OFF_LEPE, posb, attn, nullptr, 768);
    bgemm_kernel<2><<<dim3(2, ROWS / 128), 256, SMEM_DYN>>>(attn, wbf + OFF_PROJ, projb, x1, x, 256);
    ln_kernel<<<ROWS, 64>>>(x1, n2w, n2b, hs, 0);
    bgemm_kernel<3><<<dim3(8, ROWS / 128), 256, SMEM_DYN>>>(hs, wbf + OFF_FC1, fc1b, m1, nullptr, 256);
    bgemm_kernel<4><<<dim3(2, ROWS / 128), 256, SMEM_DYN>>>(m1, wbf + OFF_FC2, fc2b, out, x1, 1024);
}

// round 7
// speedup vs baseline: 3.1715x; 1.0821x over previous
#include <cuda_runtime.h>
#include <cuda_bf16.h>
#include <math.h>
#include <stdint.h>

// ---------------- problem constants ----------------
namespace {
constexpr int B_    = 32;
constexpr int NSEQ  = 4096;
constexpr int C     = 256;
constexpr int SH    = 32;
constexpr int H_    = 8;
constexpr int ROWS  = B_ * NSEQ;          // 131072
constexpr int BW    = B_ * 64;            // 2048 windows
constexpr int HID   = 1024;
constexpr float SCALE = 0.17677669529663687f;  // 32^-0.5

constexpr size_t OFF_QKVW = 0;                       // 768*256
constexpr size_t OFF_LEPE = 196608;                  // 256*768
constexpr size_t OFF_PROJ = 393216;                  // 256*256
constexpr size_t OFF_FC1  = 458752;                  // 1024*256
constexpr size_t OFF_FC2  = 720896;                  // 256*1024
constexpr size_t WBF_TOT  = 983040;

constexpr int TILE_HW = 128 * 72;               // halfwords per smem tile (144B rows)
constexpr int SMEM_DYN = 2 * 2 * TILE_HW * 2;   // 73728 B
}

// ---------------- scratch ----------------
__device__ __nv_bfloat16 g_hs  [(size_t)ROWS * C];
__device__ __nv_bfloat16 g_qkv [(size_t)ROWS * 3 * C];
__device__ __nv_bfloat16 g_attn[(size_t)ROWS * C];
__device__ __nv_bfloat16 g_lepe[(size_t)ROWS * C];
__device__ float         g_x1  [(size_t)ROWS * C];
__device__ __nv_bfloat16 g_m1  [(size_t)ROWS * HID];
__device__ __nv_bfloat16 g_wbf[WBF_TOT];

// ---------------- helpers ----------------
__device__ __forceinline__ uint32_t pack_bf2(float a, float b) {
    __nv_bfloat162 p = __floats2bfloat162_rn(a, b);
    return *reinterpret_cast<uint32_t*>(&p);
}
__device__ __forceinline__ void cpa16(uint32_t dst, const void* src) {
    asm volatile("cp.async.cg.shared.global [%0], [%1], 16;" :: "r"(dst), "l"(src));
}
__device__ __forceinline__ void cpa16_pred(uint32_t dst, const void* src, bool v) {
    int sz = v ? 16 : 0;
    asm volatile("cp.async.cg.shared.global [%0], [%1], 16, %2;"
                 :: "r"(dst), "l"(src), "r"(sz));
}
__device__ __forceinline__ void ldmx4(uint32_t& r0, uint32_t& r1, uint32_t& r2, uint32_t& r3,
                                      uint32_t addr) {
    asm volatile("ldmatrix.sync.aligned.m8n8.x4.shared.b16 {%0,%1,%2,%3}, [%4];"
                 : "=r"(r0), "=r"(r1), "=r"(r2), "=r"(r3) : "r"(addr));
}
__device__ __forceinline__ void mma16816(float* c, const uint32_t* a, const uint32_t* b) {
    asm volatile(
        "mma.sync.aligned.m16n8k16.row.col.f32.bf16.bf16.f32 "
        "{%0,%1,%2,%3}, {%4,%5,%6,%7}, {%8,%9}, {%0,%1,%2,%3};"
        : "+f"(c[0]), "+f"(c[1]), "+f"(c[2]), "+f"(c[3])
        : "r"(a[0]), "r"(a[1]), "r"(a[2]), "r"(a[3]), "r"(b[0]), "r"(b[1]));
}

// ---------------- weight conversion ----------------
__global__ void cvt_kernel(const float* __restrict__ src, __nv_bfloat16* __restrict__ dst, int n) {
    int i = blockIdx.x * 256 + threadIdx.x;
    if (i < n) dst[i] = __float2bfloat16(src[i]);
}
__global__ void posw_kernel(const float* __restrict__ pw, __nv_bfloat16* __restrict__ dst) {
    int idx = blockIdx.x * 256 + threadIdx.x;      // 196608
    int o = idx / 768, kk = idx % 768;
    int t = kk >> 8, i = kk & 255;
    dst[idx] = __float2bfloat16(pw[(size_t)o * 768 + i * 3 + t]);
}

// ---------------- LayerNorm (optional cyclic-shift read), bf16 out ----------
__global__ __launch_bounds__(64) void ln_kernel(const float* __restrict__ x,
                                                const float* __restrict__ w,
                                                const float* __restrict__ bvec,
                                                __nv_bfloat16* __restrict__ out, int shift) {
    int row = blockIdx.x;
    int b = row >> 12, n = row & 4095;
    int src = (b << 12) | ((n + shift) & 4095);
    const float4* xin = reinterpret_cast<const float4*>(x + (size_t)src * C);
    int t = threadIdx.x;
    float4 v = xin[t];
    float s = v.x + v.y + v.z + v.w;
    float q = v.x * v.x + v.y * v.y + v.z * v.z + v.w * v.w;
#pragma unroll
    for (int o = 16; o > 0; o >>= 1) {
        s += __shfl_xor_sync(0xffffffffu, s, o);
        q += __shfl_xor_sync(0xffffffffu, q, o);
    }
    __shared__ float sh[4];
    if ((t & 31) == 0) { sh[t >> 5] = s; sh[2 + (t >> 5)] = q; }
    __syncthreads();
    s = sh[0] + sh[1]; q = sh[2] + sh[3];
    float mean = s * (1.0f / C);
    float var  = q * (1.0f / C) - mean * mean;
    float rstd = rsqrtf(var + 1e-5f);
    float4 wv = reinterpret_cast<const float4*>(w)[t];
    float4 bv = reinterpret_cast<const float4*>(bvec)[t];
    uint2 pk = make_uint2(pack_bf2((v.x - mean) * rstd * wv.x + bv.x,
                                   (v.y - mean) * rstd * wv.y + bv.y),
                          pack_bf2((v.z - mean) * rstd * wv.z + bv.z,
                                   (v.w - mean) * rstd * wv.w + bv.w));
    reinterpret_cast<uint2*>(out + (size_t)row * C)[t] = pk;
}

// ---------------- windowed attention: 128 thr, 2 threads per query ---------
__global__ __launch_bounds__(128) void attn_kernel(const __nv_bfloat16* __restrict__ qkv,
                                                   const float* __restrict__ mask,
                                                   __nv_bfloat16* __restrict__ out) {
    int wh = blockIdx.x;
    int bw = wh >> 3;
    int h  = wh & 7;
    int wIdx = bw & 63;
    int t    = threadIdx.x & 63;       // query row
    int half = threadIdx.x >> 6;       // key-half 0/1

    __shared__ float ks[64][33];
    __shared__ float vs[64][33];
    __shared__ float pacc[64][33];
    __shared__ float psum[64];

    const __nv_bfloat16* rowp = qkv + ((size_t)bw * 64 + t) * 768 + h * 32;
    // half 0 loads K row t, half 1 loads V row t
    {
        const __nv_bfloat16* kv = rowp + (half ? 512 : 256);
        float* dsh = half ? &vs[t][0] : &ks[t][0];
#pragma unroll
        for (int c = 0; c < 4; c++) {
            uint4 q4 = *reinterpret_cast<const uint4*>(kv + c * 8);
            const uint32_t* w32 = &q4.x;
#pragma unroll
            for (int u = 0; u < 4; u++) {
                float2 f = __bfloat1622float2(*reinterpret_cast<const __nv_bfloat162*>(&w32[u]));
                dsh[c * 8 + u * 2 + 0] = f.x;
                dsh[c * 8 + u * 2 + 1] = f.y;
            }
        }
    }
    float qr[32];
#pragma unroll
    for (int c = 0; c < 4; c++) {
        uint4 q4 = *reinterpret_cast<const uint4*>(rowp + c * 8);
        const uint32_t* w32 = &q4.x;
#pragma unroll
        for (int u = 0; u < 4; u++) {
            float2 f = __bfloat1622float2(*reinterpret_cast<const __nv_bfloat162*>(&w32[u]));
            qr[c * 8 + u * 2 + 0] = f.x * SCALE;
            qr[c * 8 + u * 2 + 1] = f.y * SCALE;
        }
    }
    __syncthreads();

    const float* mrow = mask + ((size_t)wIdx * 64 + t) * 64 + half * 32;
    float sum = 0.f;
    float acc[32];
#pragma unroll
    for (int d = 0; d < 32; d++) acc[d] = 0.f;
#pragma unroll 2
    for (int j0 = 0; j0 < 32; j0++) {
        int j = half * 32 + j0;
        float s = mrow[j0];
#pragma unroll
        for (int d = 0; d < 32; d++) s = fmaf(qr[d], ks[j][d], s);
        float e = __expf(s);
        sum += e;
#pragma unroll
        for (int d = 0; d < 32; d++) acc[d] = fmaf(e, vs[j][d], acc[d]);
    }
    if (half) {
#pragma unroll
        for (int d = 0; d < 32; d++) pacc[t][d] = acc[d];
        psum[t] = sum;
    }
    __syncthreads();
    if (!half) {
        float inv = 1.f / (sum + psum[t]);
        __nv_bfloat16* orow = out + ((size_t)bw * 64 + t) * 256 + h * 32;
#pragma unroll
        for (int u = 0; u < 16; u++) {
            float a0 = (acc[2 * u] + pacc[t][2 * u]) * inv;
            float a1 = (acc[2 * u + 1] + pacc[t][2 * u + 1]) * inv;
            *reinterpret_cast<uint32_t*>(orow + 2 * u) = pack_bf2(a0, a1);
        }
    }
}

// ---------------- pipelined bf16 mma.sync NT GEMM, 128x128 tile, BK=64 ------
// MODE 0: QKV (bf16, ld 768) | 1: LEPE (gather A from v, bf16 store to lepe) |
// 2: PROJ (A = attn + lepe summed in loader; fp32 out, reverse shift + residual) |
// 3: FC1+GELU (bf16, ld 1024) | 4: FC2 (fp32 + residual)
template <int MODE>
__global__ __launch_bounds__(256, 1) void bgemm_kernel(
    const __nv_bfloat16* __restrict__ A, const __nv_bfloat16* __restrict__ W,
    const float* __restrict__ bias, void* __restrict__ CoutV,
    const float* __restrict__ extra, const __nv_bfloat16* __restrict__ A2, int Kin) {
    extern __shared__ __nv_bfloat16 smem[];
    const int tid  = threadIdx.x;
    const int lane = tid & 31;
    const int warp = tid >> 5;
    const int wm   = warp >> 2;
    const int wn   = warp & 3;
    const int m0 = blockIdx.y * 128;
    const int n0 = blockIdx.x * 128;

    const uint32_t sbase = (uint32_t)__cvta_generic_to_shared(smem);
    const int nslab = Kin >> 6;

    auto load_slab = [&](int s) {
        const int p = s & 1;
        const int k0 = s << 6;
        uint32_t a_s = sbase + p * (2 * TILE_HW * 2);
        uint32_t b_s = a_s + TILE_HW * 2;
#pragma unroll
        for (int i = 0; i < 4; i++) {
            int ch = tid + i * 256;
            int row = ch >> 3;
            int cb = (ch & 7) * 16;
            int colh = cb >> 1;
            uint32_t doff = row * 144 + cb;
            if (MODE == 1) {
                int d = (k0 >> 8) - 1;
                int R = m0 + row;
                bool v = ((unsigned)((R & 63) + d) < 64u);
                const __nv_bfloat16* src =
                    v ? (A + (size_t)(R + d) * 768 + ((k0 + colh) & 255)) : A;
                cpa16_pred(a_s + doff, src, v);
            } else if (MODE == 2) {
                // A = attn + lepe, summed here (bf16x2)
                size_t o = (size_t)(m0 + row) * Kin + k0 + colh;
                uint4 a4 = *reinterpret_cast<const uint4*>(A + o);
                uint4 l4 = *reinterpret_cast<const uint4*>(A2 + o);
                uint32_t* xa = &a4.x;
                const uint32_t* xl = &l4.x;
#pragma unroll
                for (int u = 0; u < 4; u++) {
                    __nv_bfloat162 s2 =
                        __hadd2(*reinterpret_cast<__nv_bfloat162*>(&xa[u]),
                                *reinterpret_cast<const __nv_bfloat162*>(&xl[u]));
                    xa[u] = *reinterpret_cast<uint32_t*>(&s2);
                }
                *reinterpret_cast<uint4*>(
                    reinterpret_cast<char*>(smem) + p * (2 * TILE_HW * 2) + doff) = a4;
            } else {
                cpa16(a_s + doff, A + (size_t)(m0 + row) * Kin + k0 + colh);
            }
            cpa16(b_s + doff, W + (size_t)(n0 + row) * Kin + k0 + colh);
        }
        asm volatile("cp.async.commit_group;" ::: "memory");
    };

    float c[4][4][4];
#pragma unroll
    for (int i = 0; i < 4; i++)
#pragma unroll
        for (int j = 0; j < 4; j++)
#pragma unroll
            for (int r = 0; r < 4; r++) c[i][j][r] = 0.f;

    load_slab(0);
    for (int s = 0; s < nslab; s++) {
        if (s + 1 < nslab) {
            load_slab(s + 1);
            asm volatile("cp.async.wait_group 1;" ::: "memory");
        } else {
            asm volatile("cp.async.wait_group 0;" ::: "memory");
        }
        __syncthreads();

        const int p = s & 1;
        uint32_t a_s = sbase + p * (2 * TILE_HW * 2);
        uint32_t b_s = a_s + TILE_HW * 2;
#pragma unroll
        for (int ks = 0; ks < 4; ks++) {
            const int kk = ks * 16;
            uint32_t a[4][4], b[4][2];
#pragma unroll
            for (int i = 0; i < 4; i++) {
                int row = wm * 64 + i * 16 + (lane & 15);
                int col = kk + ((lane >> 4) << 3);
                ldmx4(a[i][0], a[i][1], a[i][2], a[i][3], a_s + row * 144 + col * 2);
            }
#pragma unroll
            for (int jj = 0; jj < 2; jj++) {
                int row = wn * 32 + jj * 16 + (lane & 7) + ((lane >> 4) << 3);
                int col = kk + (((lane >> 3) & 1) << 3);
                ldmx4(b[2 * jj][0], b[2 * jj][1], b[2 * jj + 1][0], b[2 * jj + 1][1],
                      b_s + row * 144 + col * 2);
            }
#pragma unroll
            for (int i = 0; i < 4; i++)
#pragma unroll
                for (int j = 0; j < 4; j++) mma16816(c[i][j], a[i], b[j]);
        }
        __syncthreads();
    }

    // epilogue
#pragma unroll
    for (int i = 0; i < 4; i++) {
        int r_base = m0 + wm * 64 + i * 16 + (lane >> 2);
#pragma unroll
        for (int j = 0; j < 4; j++) {
            int col = n0 + wn * 32 + j * 8 + (lane & 3) * 2;
            float2 bv = *reinterpret_cast<const float2*>(bias + col);
#pragma unroll
            for (int hh = 0; hh < 2; hh++) {
                int r = r_base + hh * 8;
                float v0 = c[i][j][hh * 2 + 0] + bv.x;
                float v1 = c[i][j][hh * 2 + 1] + bv.y;
                if (MODE == 0) {
                    __nv_bfloat16* Cb = (__nv_bfloat16*)CoutV;
                    *reinterpret_cast<uint32_t*>(Cb + (size_t)r * 768 + col) = pack_bf2(v0, v1);
                } else if (MODE == 1) {
                    __nv_bfloat16* Cb = (__nv_bfloat16*)CoutV;
                    *reinterpret_cast<uint32_t*>(Cb + (size_t)r * 256 + col) = pack_bf2(v0, v1);
                } else if (MODE == 2) {
                    float* Cf = (float*)CoutV;
                    int b = r >> 12, n = r & 4095;
                    int n2 = (n + SH) & 4095;
                    size_t o = ((size_t)((b << 12) | n2)) * 256 + col;
                    float2 e = *reinterpret_cast<const float2*>(extra + o);
                    *reinterpret_cast<float2*>(Cf + o) = make_float2(e.x + v0, e.y + v1);
                } else if (MODE == 3) {
                    __nv_bfloat16* Cb = (__nv_bfloat16*)CoutV;
                    float g0 = 0.5f * v0 * (1.f + erff(v0 * 0.70710678118654752f));
                    float g1 = 0.5f * v1 * (1.f + erff(v1 * 0.70710678118654752f));
                    *reinterpret_cast<uint32_t*>(Cb + (size_t)r * 1024 + col) = pack_bf2(g0, g1);
                } else {
                    float* Cf = (float*)CoutV;
                    size_t o = (size_t)r * 256 + col;
                    float2 e = *reinterpret_cast<const float2*>(extra + o);
                    *reinterpret_cast<float2*>(Cf + o) = make_float2(v0 + e.x, v1 + e.y);
                }
            }
        }
    }
}

// ---------------- launch ----------------
extern "C" void kernel_launch(void* const* d_in, const int* in_sizes, int n_in,
                              void* d_out, int out_size) {
    const float* x     = (const float*)d_in[0];
    const float* mask  = (const float*)d_in[1];
    const float* n1w   = (const float*)d_in[2];
    const float* n1b   = (const float*)d_in[3];
    const float* qkvw  = (const float*)d_in[4];
    const float* qkvb  = (const float*)d_in[5];
    const float* posw  = (const float*)d_in[6];
    const float* posb  = (const float*)d_in[7];
    const float* projw = (const float*)d_in[8];
    const float* projb = (const float*)d_in[9];
    const float* n2w   = (const float*)d_in[10];
    const float* n2b   = (const float*)d_in[11];
    const float* fc1w  = (const float*)d_in[12];
    const float* fc1b  = (const float*)d_in[13];
    const float* fc2w  = (const float*)d_in[14];
    const float* fc2b  = (const float*)d_in[15];
    float* out = (float*)d_out;

    __nv_bfloat16 *hs, *qkv, *attn, *lepe, *m1, *wbf;
    float *x1;
    cudaGetSymbolAddress((void**)&hs,   g_hs);
    cudaGetSymbolAddress((void**)&qkv,  g_qkv);
    cudaGetSymbolAddress((void**)&attn, g_attn);
    cudaGetSymbolAddress((void**)&lepe, g_lepe);
    cudaGetSymbolAddress((void**)&x1,   g_x1);
    cudaGetSymbolAddress((void**)&m1,   g_m1);
    cudaGetSymbolAddress((void**)&wbf,  g_wbf);

    static cudaStream_t s_side = nullptr;
    static cudaEvent_t evA = nullptr, evB = nullptr;
    static bool attr_done = false;
    if (!attr_done) {
        cudaFuncSetAttribute(bgemm_kernel<0>, cudaFuncAttributeMaxDynamicSharedMemorySize, SMEM_DYN);
        cudaFuncSetAttribute(bgemm_kernel<1>, cudaFuncAttributeMaxDynamicSharedMemorySize, SMEM_DYN);
        cudaFuncSetAttribute(bgemm_kernel<2>, cudaFuncAttributeMaxDynamicSharedMemorySize, SMEM_DYN);
        cudaFuncSetAttribute(bgemm_kernel<3>, cudaFuncAttributeMaxDynamicSharedMemorySize, SMEM_DYN);
        cudaFuncSetAttribute(bgemm_kernel<4>, cudaFuncAttributeMaxDynamicSharedMemorySize, SMEM_DYN);
        cudaStreamCreateWithFlags(&s_side, cudaStreamNonBlocking);
        cudaEventCreateWithFlags(&evA, cudaEventDisableTiming);
        cudaEventCreateWithFlags(&evB, cudaEventDisableTiming);
        attr_done = true;
    }

    cvt_kernel<<<768, 256>>>(qkvw,  wbf + OFF_QKVW, 196608);
    posw_kernel<<<768, 256>>>(posw, wbf + OFF_LEPE);
    cvt_kernel<<<256, 256>>>(projw, wbf + OFF_PROJ, 65536);
    cvt_kernel<<<1024, 256>>>(fc1w, wbf + OFF_FC1, 262144);
    cvt_kernel<<<1024, 256>>>(fc2w, wbf + OFF_FC2, 262144);

    ln_kernel<<<ROWS, 64>>>(x, n1w, n1b, hs, SH);
    bgemm_kernel<0><<<dim3(6, ROWS / 128), 256, SMEM_DYN>>>(
        hs, wbf + OFF_QKVW, qkvb, qkv, nullptr, nullptr, 256);

    // fork: attention on side stream, LePE GEMM on main stream (independent)
    cudaEventRecord(evA, 0);
    cudaStreamWaitEvent(s_side, evA, 0);
    attn_kernel<<<BW * H_, 128, 0, s_side>>>(qkv, mask, attn);
    cudaEventRecord(evB, s_side);

    bgemm_kernel<1><<<dim3(2, ROWS / 128), 256, SMEM_DYN>>>(
        qkv + 512, wbf + OFF_LEPE, posb, lepe, nullptr, nullptr, 768);

    // join: proj needs both attn and lepe
    cudaStreamWaitEvent(0, evB, 0);
    bgemm_kernel<2><<<dim3(2, ROWS / 128), 256, SMEM_DYN>>>(
        attn, wbf + OFF_PROJ, projb, x1, x, lepe, 256);

    ln_kernel<<<ROWS, 64>>>(x1, n2w, n2b, hs, 0);
    bgemm_kernel<3><<<dim3(8, ROWS / 128), 256, SMEM_DYN>>>(
        hs, wbf + OFF_FC1, fc1b, m1, nullptr, nullptr, 256);
    bgemm_kernel<4><<<dim3(2, ROWS / 128), 256, SMEM_DYN>>>(
        m1, wbf + OFF_FC2, fc2b, out, x1, nullptr, 1024);
}

// round 9
// speedup vs baseline: 3.6474x; 1.1500x over previous
#include <cuda_runtime.h>
#include <cuda_bf16.h>
#include <math.h>
#include <stdint.h>

// ---------------- problem constants ----------------
namespace {
constexpr int B_    = 32;
constexpr int NSEQ  = 4096;
constexpr int C     = 256;
constexpr int SH    = 32;
constexpr int H_    = 8;
constexpr int ROWS  = B_ * NSEQ;          // 131072
constexpr int BW    = B_ * 64;            // 2048 windows
constexpr int HID   = 1024;
constexpr float SCALE = 0.17677669529663687f;  // 32^-0.5

constexpr size_t OFF_QKVW = 0;                       // 768*256
constexpr size_t OFF_LEPE = 196608;                  // 256*768
constexpr size_t OFF_PROJ = 393216;                  // 256*256
constexpr size_t OFF_FC1  = 458752;                  // 1024*256
constexpr size_t OFF_FC2  = 720896;                  // 256*1024
constexpr size_t WBF_TOT  = 983040;

constexpr int TILE_HW = 128 * 72;               // halfwords per smem tile (144B rows)
constexpr int SMEM_DYN = 2 * 2 * TILE_HW * 2;   // 73728 B
}

// ---------------- scratch ----------------
__device__ __nv_bfloat16 g_hs  [(size_t)ROWS * C];
__device__ __nv_bfloat16 g_qkv [(size_t)ROWS * 3 * C];
__device__ __nv_bfloat16 g_attn[(size_t)ROWS * C];
__device__ __nv_bfloat16 g_lepe[(size_t)ROWS * C];
__device__ float         g_x1  [(size_t)ROWS * C];
__device__ __nv_bfloat16 g_m1  [(size_t)ROWS * HID];
__device__ __nv_bfloat16 g_wbf[WBF_TOT];

// ---------------- helpers ----------------
__device__ __forceinline__ uint32_t pack_bf2(float a, float b) {
    __nv_bfloat162 p = __floats2bfloat162_rn(a, b);
    return *reinterpret_cast<uint32_t*>(&p);
}
__device__ __forceinline__ void cpa16(uint32_t dst, const void* src) {
    asm volatile("cp.async.cg.shared.global [%0], [%1], 16;" :: "r"(dst), "l"(src));
}
__device__ __forceinline__ void cpa16_pred(uint32_t dst, const void* src, bool v) {
    int sz = v ? 16 : 0;
    asm volatile("cp.async.cg.shared.global [%0], [%1], 16, %2;"
                 :: "r"(dst), "l"(src), "r"(sz));
}
__device__ __forceinline__ void ldmx4(uint32_t& r0, uint32_t& r1, uint32_t& r2, uint32_t& r3,
                                      uint32_t addr) {
    asm volatile("ldmatrix.sync.aligned.m8n8.x4.shared.b16 {%0,%1,%2,%3}, [%4];"
                 : "=r"(r0), "=r"(r1), "=r"(r2), "=r"(r3) : "r"(addr));
}
__device__ __forceinline__ void mma16816(float* c, const uint32_t* a, const uint32_t* b) {
    asm volatile(
        "mma.sync.aligned.m16n8k16.row.col.f32.bf16.bf16.f32 "
        "{%0,%1,%2,%3}, {%4,%5,%6,%7}, {%8,%9}, {%0,%1,%2,%3};"
        : "+f"(c[0]), "+f"(c[1]), "+f"(c[2]), "+f"(c[3])
        : "r"(a[0]), "r"(a[1]), "r"(a[2]), "r"(a[3]), "r"(b[0]), "r"(b[1]));
}

// ---------------- weight conversion ----------------
__global__ void cvt_kernel(const float* __restrict__ src, __nv_bfloat16* __restrict__ dst, int n) {
    int i = blockIdx.x * 256 + threadIdx.x;
    if (i < n) dst[i] = __float2bfloat16(src[i]);
}
__global__ void posw_kernel(const float* __restrict__ pw, __nv_bfloat16* __restrict__ dst) {
    int idx = blockIdx.x * 256 + threadIdx.x;      // 196608
    int o = idx / 768, kk = idx % 768;
    int t = kk >> 8, i = kk & 255;
    dst[idx] = __float2bfloat16(pw[(size_t)o * 768 + i * 3 + t]);
}

// ---------------- LayerNorm (optional cyclic-shift read), bf16 out ----------
__global__ __launch_bounds__(64) void ln_kernel(const float* __restrict__ x,
                                                const float* __restrict__ w,
                                                const float* __restrict__ bvec,
                                                __nv_bfloat16* __restrict__ out, int shift) {
    int row = blockIdx.x;
    int b = row >> 12, n = row & 4095;
    int src = (b << 12) | ((n + shift) & 4095);
    const float4* xin = reinterpret_cast<const float4*>(x + (size_t)src * C);
    int t = threadIdx.x;
    float4 v = xin[t];
    float s = v.x + v.y + v.z + v.w;
    float q = v.x * v.x + v.y * v.y + v.z * v.z + v.w * v.w;
#pragma unroll
    for (int o = 16; o > 0; o >>= 1) {
        s += __shfl_xor_sync(0xffffffffu, s, o);
        q += __shfl_xor_sync(0xffffffffu, q, o);
    }
    __shared__ float sh[4];
    if ((t & 31) == 0) { sh[t >> 5] = s; sh[2 + (t >> 5)] = q; }
    __syncthreads();
    s = sh[0] + sh[1]; q = sh[2] + sh[3];
    float mean = s * (1.0f / C);
    float var  = q * (1.0f / C) - mean * mean;
    float rstd = rsqrtf(var + 1e-5f);
    float4 wv = reinterpret_cast<const float4*>(w)[t];
    float4 bv = reinterpret_cast<const float4*>(bvec)[t];
    uint2 pk = make_uint2(pack_bf2((v.x - mean) * rstd * wv.x + bv.x,
                                   (v.y - mean) * rstd * wv.y + bv.y),
                          pack_bf2((v.z - mean) * rstd * wv.z + bv.z,
                                   (v.w - mean) * rstd * wv.w + bv.w));
    reinterpret_cast<uint2*>(out + (size_t)row * C)[t] = pk;
}

// ---------------- windowed attention: 128 thr, 2 threads per query ---------
__global__ __launch_bounds__(128) void attn_kernel(const __nv_bfloat16* __restrict__ qkv,
                                                   const float* __restrict__ mask,
                                                   __nv_bfloat16* __restrict__ out) {
    int wh = blockIdx.x;
    int bw = wh >> 3;
    int h  = wh & 7;
    int wIdx = bw & 63;
    int t    = threadIdx.x & 63;       // query row
    int half = threadIdx.x >> 6;       // key-half 0/1

    __shared__ float ks[64][33];
    __shared__ float vs[64][33];
    __shared__ float pacc[64][33];
    __shared__ float psum[64];

    const __nv_bfloat16* rowp = qkv + ((size_t)bw * 64 + t) * 768 + h * 32;
    {
        const __nv_bfloat16* kv = rowp + (half ? 512 : 256);
        float* dsh = half ? &vs[t][0] : &ks[t][0];
#pragma unroll
        for (int c = 0; c < 4; c++) {
            uint4 q4 = *reinterpret_cast<const uint4*>(kv + c * 8);
            const uint32_t* w32 = &q4.x;
#pragma unroll
            for (int u = 0; u < 4; u++) {
                float2 f = __bfloat1622float2(*reinterpret_cast<const __nv_bfloat162*>(&w32[u]));
                dsh[c * 8 + u * 2 + 0] = f.x;
                dsh[c * 8 + u * 2 + 1] = f.y;
            }
        }
    }
    float qr[32];
#pragma unroll
    for (int c = 0; c < 4; c++) {
        uint4 q4 = *reinterpret_cast<const uint4*>(rowp + c * 8);
        const uint32_t* w32 = &q4.x;
#pragma unroll
        for (int u = 0; u < 4; u++) {
            float2 f = __bfloat1622float2(*reinterpret_cast<const __nv_bfloat162*>(&w32[u]));
            qr[c * 8 + u * 2 + 0] = f.x * SCALE;
            qr[c * 8 + u * 2 + 1] = f.y * SCALE;
        }
    }
    __syncthreads();

    const float* mrow = mask + ((size_t)wIdx * 64 + t) * 64 + half * 32;
    float sum = 0.f;
    float acc[32];
#pragma unroll
    for (int d = 0; d < 32; d++) acc[d] = 0.f;
#pragma unroll 2
    for (int j0 = 0; j0 < 32; j0++) {
        int j = half * 32 + j0;
        float s = mrow[j0];
#pragma unroll
        for (int d = 0; d < 32; d++) s = fmaf(qr[d], ks[j][d], s);
        float e = __expf(s);
        sum += e;
#pragma unroll
        for (int d = 0; d < 32; d++) acc[d] = fmaf(e, vs[j][d], acc[d]);
    }
    if (half) {
#pragma unroll
        for (int d = 0; d < 32; d++) pacc[t][d] = acc[d];
        psum[t] = sum;
    }
    __syncthreads();
    if (!half) {
        float inv = 1.f / (sum + psum[t]);
        __nv_bfloat16* orow = out + ((size_t)bw * 64 + t) * 256 + h * 32;
#pragma unroll
        for (int u = 0; u < 16; u++) {
            float a0 = (acc[2 * u] + pacc[t][2 * u]) * inv;
            float a1 = (acc[2 * u + 1] + pacc[t][2 * u + 1]) * inv;
            *reinterpret_cast<uint32_t*>(orow + 2 * u) = pack_bf2(a0, a1);
        }
    }
}

// ---------------- pipelined bf16 mma.sync NT GEMM, 128x128 tile, BK=64 ------
// MODE 0: QKV (bf16, ld 768) | 1: LEPE (gather A from v, bf16 store to lepe) |
// 2: PROJ (A = attn + lepe summed in loader; fp32 out, reverse shift + residual) |
// 3: FC1+GELU (bf16, ld 1024) | 4: FC2 (fp32 + residual)
template <int MODE>
__global__ __launch_bounds__(256, 2) void bgemm_kernel(
    const __nv_bfloat16* __restrict__ A, const __nv_bfloat16* __restrict__ W,
    const float* __restrict__ bias, void* __restrict__ CoutV,
    const float* __restrict__ extra, const __nv_bfloat16* __restrict__ A2, int Kin) {
    extern __shared__ __nv_bfloat16 smem[];
    const int tid  = threadIdx.x;
    const int lane = tid & 31;
    const int warp = tid >> 5;
    const int wm   = warp >> 2;
    const int wn   = warp & 3;
    const int m0 = blockIdx.y * 128;
    const int n0 = blockIdx.x * 128;

    const uint32_t sbase = (uint32_t)__cvta_generic_to_shared(smem);
    const int nslab = Kin >> 6;

    auto load_slab = [&](int s) {
        const int p = s & 1;
        const int k0 = s << 6;
        uint32_t a_s = sbase + p * (2 * TILE_HW * 2);
        uint32_t b_s = a_s + TILE_HW * 2;
#pragma unroll
        for (int i = 0; i < 4; i++) {
            int ch = tid + i * 256;
            int row = ch >> 3;
            int cb = (ch & 7) * 16;
            int colh = cb >> 1;
            uint32_t doff = row * 144 + cb;
            if (MODE == 1) {
                int d = (k0 >> 8) - 1;
                int R = m0 + row;
                bool v = ((unsigned)((R & 63) + d) < 64u);
                const __nv_bfloat16* src =
                    v ? (A + (size_t)(R + d) * 768 + ((k0 + colh) & 255)) : A;
                cpa16_pred(a_s + doff, src, v);
            } else if (MODE == 2) {
                size_t o = (size_t)(m0 + row) * Kin + k0 + colh;
                uint4 a4 = *reinterpret_cast<const uint4*>(A + o);
                uint4 l4 = *reinterpret_cast<const uint4*>(A2 + o);
                uint32_t* xa = &a4.x;
                const uint32_t* xl = &l4.x;
#pragma unroll
                for (int u = 0; u < 4; u++) {
                    __nv_bfloat162 s2 =
                        __hadd2(*reinterpret_cast<__nv_bfloat162*>(&xa[u]),
                                *reinterpret_cast<const __nv_bfloat162*>(&xl[u]));
                    xa[u] = *reinterpret_cast<uint32_t*>(&s2);
                }
                *reinterpret_cast<uint4*>(
                    reinterpret_cast<char*>(smem) + p * (2 * TILE_HW * 2) + doff) = a4;
            } else {
                cpa16(a_s + doff, A + (size_t)(m0 + row) * Kin + k0 + colh);
            }
            cpa16(b_s + doff, W + (size_t)(n0 + row) * Kin + k0 + colh);
        }
        asm volatile("cp.async.commit_group;" ::: "memory");
    };

    float c[4][4][4];
#pragma unroll
    for (int i = 0; i < 4; i++)
#pragma unroll
        for (int j = 0; j < 4; j++)
#pragma unroll
            for (int r = 0; r < 4; r++) c[i][j][r] = 0.f;

    load_slab(0);
    for (int s = 0; s < nslab; s++) {
        if (s + 1 < nslab) {
            load_slab(s + 1);
            asm volatile("cp.async.wait_group 1;" ::: "memory");
        } else {
            asm volatile("cp.async.wait_group 0;" ::: "memory");
        }
        __syncthreads();

        const int p = s & 1;
        uint32_t a_s = sbase + p * (2 * TILE_HW * 2);
        uint32_t b_s = a_s + TILE_HW * 2;
#pragma unroll
        for (int ks = 0; ks < 4; ks++) {
            const int kk = ks * 16;
            uint32_t a[4][4], b[4][2];
#pragma unroll
            for (int i = 0; i < 4; i++) {
                int row = wm * 64 + i * 16 + (lane & 15);
                int col = kk + ((lane >> 4) << 3);
                ldmx4(a[i][0], a[i][1], a[i][2], a[i][3], a_s + row * 144 + col * 2);
            }
#pragma unroll
            for (int jj = 0; jj < 2; jj++) {
                int row = wn * 32 + jj * 16 + (lane & 7) + ((lane >> 4) << 3);
                int col = kk + (((lane >> 3) & 1) << 3);
                ldmx4(b[2 * jj][0], b[2 * jj][1], b[2 * jj + 1][0], b[2 * jj + 1][1],
                      b_s + row * 144 + col * 2);
            }
#pragma unroll
            for (int i = 0; i < 4; i++)
#pragma unroll
                for (int j = 0; j < 4; j++) mma16816(c[i][j], a[i], b[j]);
        }
        __syncthreads();
    }

    // epilogue
#pragma unroll
    for (int i = 0; i < 4; i++) {
        int r_base = m0 + wm * 64 + i * 16 + (lane >> 2);
#pragma unroll
        for (int j = 0; j < 4; j++) {
            int col = n0 + wn * 32 + j * 8 + (lane & 3) * 2;
            float2 bv = *reinterpret_cast<const float2*>(bias + col);
#pragma unroll
            for (int hh = 0; hh < 2; hh++) {
                int r = r_base + hh * 8;
                float v0 = c[i][j][hh * 2 + 0] + bv.x;
                float v1 = c[i][j][hh * 2 + 1] + bv.y;
                if (MODE == 0) {
                    __nv_bfloat16* Cb = (__nv_bfloat16*)CoutV;
                    *reinterpret_cast<uint32_t*>(Cb + (size_t)r * 768 + col) = pack_bf2(v0, v1);
                } else if (MODE == 1) {
                    __nv_bfloat16* Cb = (__nv_bfloat16*)CoutV;
                    *reinterpret_cast<uint32_t*>(Cb + (size_t)r * 256 + col) = pack_bf2(v0, v1);
                } else if (MODE == 2) {
                    float* Cf = (float*)CoutV;
                    int b = r >> 12, n = r & 4095;
                    int n2 = (n + SH) & 4095;
                    size_t o = ((size_t)((b << 12) | n2)) * 256 + col;
                    float2 e = *reinterpret_cast<const float2*>(extra + o);
                    *reinterpret_cast<float2*>(Cf + o) = make_float2(e.x + v0, e.y + v1);
                } else if (MODE == 3) {
                    __nv_bfloat16* Cb = (__nv_bfloat16*)CoutV;
                    float g0 = 0.5f * v0 * (1.f + erff(v0 * 0.70710678118654752f));
                    float g1 = 0.5f * v1 * (1.f + erff(v1 * 0.70710678118654752f));
                    *reinterpret_cast<uint32_t*>(Cb + (size_t)r * 1024 + col) = pack_bf2(g0, g1);
                } else {
                    float* Cf = (float*)CoutV;
                    size_t o = (size_t)r * 256 + col;
                    float2 e = *reinterpret_cast<const float2*>(extra + o);
                    *reinterpret_cast<float2*>(Cf + o) = make_float2(v0 + e.x, v1 + e.y);
                }
            }
        }
    }
}

// ---------------- launch ----------------
extern "C" void kernel_launch(void* const* d_in, const int* in_sizes, int n_in,
                              void* d_out, int out_size) {
    const float* x     = (const float*)d_in[0];
    const float* mask  = (const float*)d_in[1];
    const float* n1w   = (const float*)d_in[2];
    const float* n1b   = (const float*)d_in[3];
    const float* qkvw  = (const float*)d_in[4];
    const float* qkvb  = (const float*)d_in[5];
    const float* posw  = (const float*)d_in[6];
    const float* posb  = (const float*)d_in[7];
    const float* projw = (const float*)d_in[8];
    const float* projb = (const float*)d_in[9];
    const float* n2w   = (const float*)d_in[10];
    const float* n2b   = (const float*)d_in[11];
    const float* fc1w  = (const float*)d_in[12];
    const float* fc1b  = (const float*)d_in[13];
    const float* fc2w  = (const float*)d_in[14];
    const float* fc2b  = (const float*)d_in[15];
    float* out = (float*)d_out;

    __nv_bfloat16 *hs, *qkv, *attn, *lepe, *m1, *wbf;
    float *x1;
    cudaGetSymbolAddress((void**)&hs,   g_hs);
    cudaGetSymbolAddress((void**)&qkv,  g_qkv);
    cudaGetSymbolAddress((void**)&attn, g_attn);
    cudaGetSymbolAddress((void**)&lepe, g_lepe);
    cudaGetSymbolAddress((void**)&x1,   g_x1);
    cudaGetSymbolAddress((void**)&m1,   g_m1);
    cudaGetSymbolAddress((void**)&wbf,  g_wbf);

    static cudaStream_t s_side = nullptr;
    static cudaEvent_t evStart = nullptr, evA = nullptr, evB = nullptr, evC = nullptr;
    static bool attr_done = false;
    if (!attr_done) {
        cudaFuncSetAttribute(bgemm_kernel<0>, cudaFuncAttributeMaxDynamicSharedMemorySize, SMEM_DYN);
        cudaFuncSetAttribute(bgemm_kernel<1>, cudaFuncAttributeMaxDynamicSharedMemorySize, SMEM_DYN);
        cudaFuncSetAttribute(bgemm_kernel<2>, cudaFuncAttributeMaxDynamicSharedMemorySize, SMEM_DYN);
        cudaFuncSetAttribute(bgemm_kernel<3>, cudaFuncAttributeMaxDynamicSharedMemorySize, SMEM_DYN);
        cudaFuncSetAttribute(bgemm_kernel<4>, cudaFuncAttributeMaxDynamicSharedMemorySize, SMEM_DYN);
        cudaStreamCreateWithFlags(&s_side, cudaStreamNonBlocking);
        cudaEventCreateWithFlags(&evStart, cudaEventDisableTiming);
        cudaEventCreateWithFlags(&evA, cudaEventDisableTiming);
        cudaEventCreateWithFlags(&evB, cudaEventDisableTiming);
        cudaEventCreateWithFlags(&evC, cudaEventDisableTiming);
        attr_done = true;
    }

    // fork side stream FROM the capture-origin stream before using it
    cudaEventRecord(evStart, 0);
    cudaStreamWaitEvent(s_side, evStart, 0);

    // weight conversions on side stream, overlapped with LN1 on main
    cvt_kernel<<<768, 256, 0, s_side>>>(qkvw,  wbf + OFF_QKVW, 196608);
    posw_kernel<<<768, 256, 0, s_side>>>(posw, wbf + OFF_LEPE);
    cvt_kernel<<<256, 256, 0, s_side>>>(projw, wbf + OFF_PROJ, 65536);
    cvt_kernel<<<1024, 256, 0, s_side>>>(fc1w, wbf + OFF_FC1, 262144);
    cvt_kernel<<<1024, 256, 0, s_side>>>(fc2w, wbf + OFF_FC2, 262144);
    cudaEventRecord(evC, s_side);

    ln_kernel<<<ROWS, 64>>>(x, n1w, n1b, hs, SH);
    cudaStreamWaitEvent(0, evC, 0);
    bgemm_kernel<0><<<dim3(6, ROWS / 128), 256, SMEM_DYN>>>(
        hs, wbf + OFF_QKVW, qkvb, qkv, nullptr, nullptr, 256);

    // fork: attention on side stream, LePE GEMM on main stream (independent)
    cudaEventRecord(evA, 0);
    cudaStreamWaitEvent(s_side, evA, 0);
    attn_kernel<<<BW * H_, 128, 0, s_side>>>(qkv, mask, attn);
    cudaEventRecord(evB, s_side);

    bgemm_kernel<1><<<dim3(2, ROWS / 128), 256, SMEM_DYN>>>(
        qkv + 512, wbf + OFF_LEPE, posb, lepe, nullptr, nullptr, 768);

    // join: proj needs both attn and lepe
    cudaStreamWaitEvent(0, evB, 0);
    bgemm_kernel<2><<<dim3(2, ROWS / 128), 256, SMEM_DYN>>>(
        attn, wbf + OFF_PROJ, projb, x1, x, lepe, 256);

    ln_kernel<<<ROWS, 64>>>(x1, n2w, n2b, hs, 0);
    bgemm_kernel<3><<<dim3(8, ROWS / 128), 256, SMEM_DYN>>>(
        hs, wbf + OFF_FC1, fc1b, m1, nullptr, nullptr, 256);
    bgemm_kernel<4><<<dim3(2, ROWS / 128), 256, SMEM_DYN>>>(
        m1, wbf + OFF_FC2, fc2b, out, x1, nullptr, 1024);
}